// round 15
// baseline (speedup 1.0000x reference)
#include <cuda_runtime.h>
#include <cuda_bf16.h>
#include <cstdint>

#define NB 4
#define NS 2048
#define NE 1024
#define NH 16
#define ND 64

#if defined(__CUDA_ARCH__) && (defined(__CUDA_ARCH_FEAT_SM103_ALL) || \
    defined(__CUDA_ARCH_SPECIFIC__))
#define HAS_TCGEN05 1
#else
#define HAS_TCGEN05 0
#endif

// ---------------------------------------------------------------------------
// Device globals (scratch)
// ---------------------------------------------------------------------------
__device__ __align__(256) float g_v[NB * NH * NS * ND];
__device__ __align__(256) __nv_bfloat16 g_qh[NB * NH * NS * ND];
__device__ __align__(256) __nv_bfloat16 g_ql[NB * NH * NS * ND];
__device__ __align__(256) __nv_bfloat16 g_kh[NB * NH * NS * ND];
__device__ __align__(256) __nv_bfloat16 g_kl[NB * NH * NS * ND];
__device__ __align__(256) __nv_bfloat16 g_vth[NB * NH * ND * NS];
__device__ __align__(256) __nv_bfloat16 g_vtl[NB * NH * ND * NS];
__device__ __align__(256) __nv_bfloat16 g_ah[NB * NS * NE];       // ctx hi/lo
__device__ __align__(256) __nv_bfloat16 g_al[NB * NS * NE];
// weights, pre-tiled+swizzled: [z][n_block(4)][k_chunk(16)][32KB tile]
__device__ __align__(256) __nv_bfloat16 g_wth[3][NE * NE];
__device__ __align__(256) __nv_bfloat16 g_wtl[3][NE * NE];

// ---------------------------------------------------------------------------
// PTX helpers
// ---------------------------------------------------------------------------
__device__ __forceinline__ uint32_t smem_u32(const void* p) {
    uint32_t a;
    asm("{ .reg .u64 t; cvta.to.shared.u64 t, %1; cvt.u32.u64 %0, t; }"
        : "=r"(a) : "l"(p));
    return a;
}
__device__ __forceinline__ uint32_t elect_one() {
    uint32_t pred;
    asm volatile("{ .reg .pred p; elect.sync _|p, 0xFFFFFFFF; selp.b32 %0,1,0,p; }"
                 : "=r"(pred));
    return pred;
}
#define MBARRIER_INIT(addr, cnt) \
    asm volatile("mbarrier.init.shared.b64 [%0], %1;" :: "r"(addr), "r"(cnt) : "memory")
#define MBARRIER_EXPECT_TX(addr, bytes) \
    asm volatile("mbarrier.arrive.expect_tx.shared.b64 _, [%0], %1;" \
        :: "r"((uint32_t)(addr)), "r"((uint32_t)(bytes)) : "memory")
#define MBARRIER_WAIT_PARITY(addr, par) do {                                   \
    uint32_t _m = (addr), _p = (par), _d;                                      \
    asm volatile("{ .reg .pred p; mbarrier.try_wait.parity.acquire.cta.shared::cta.b64 p, [%1], %2; selp.b32 %0,1,0,p; }" \
        : "=r"(_d) : "r"(_m), "r"(_p) : "memory");                             \
    if (!_d) {                                                                 \
        asm volatile("{ .reg .pred P1; WL_%=: mbarrier.try_wait.parity.acquire.cta.shared::cta.b64 P1, [%0], %1, 0x989680; @P1 bra.uni WD_%=; bra.uni WL_%=; WD_%=: }" \
            :: "r"(_m), "r"(_p) : "memory");                                   \
    } } while (0)
#define CP_BULK(dst, src, bytes, mbar) \
    asm volatile("cp.async.bulk.shared::cluster.global.mbarrier::complete_tx::bytes [%0], [%1], %2, [%3];" \
        :: "r"((uint32_t)(dst)), "l"(src), "r"((uint32_t)(bytes)), \
           "r"((uint32_t)(mbar)) : "memory")
#define TCGEN05_ALLOC(saddr, ncols) \
    asm volatile("tcgen05.alloc.cta_group::1.sync.aligned.shared::cta.b32 [%0], %1;" \
        :: "r"((uint32_t)(saddr)), "r"((uint32_t)(ncols)) : "memory")
#define TCGEN05_DEALLOC(tmem, ncols) \
    asm volatile("tcgen05.dealloc.cta_group::1.sync.aligned.b32 %0, %1;" \
        :: "r"(tmem), "r"((uint32_t)(ncols)))
#define TCGEN05_COMMIT(mbar) \
    asm volatile("tcgen05.commit.cta_group::1.mbarrier::arrive::one.shared::cluster.b64 [%0];" \
        :: "r"((uint32_t)(mbar)) : "memory")
#define TCGEN05_WAIT_LD() asm volatile("tcgen05.wait::ld.sync.aligned;" ::: "memory")
#define TCGEN05_WAIT_ST() asm volatile("tcgen05.wait::st.sync.aligned;" ::: "memory")
#define TCGEN05_FENCE_AFTER() asm volatile("tcgen05.fence::after_thread_sync;" ::: "memory")
#define TCGEN05_FENCE_BEFORE() asm volatile("tcgen05.fence::before_thread_sync;" ::: "memory")
#define FENCE_ASYNC() asm volatile("fence.proxy.async.shared::cta;" ::: "memory")

#define TCGEN05_LD_X32(r, ta)                                                  \
    asm volatile("tcgen05.ld.sync.aligned.32x32b.x32.b32 "                     \
        "{%0,%1,%2,%3,%4,%5,%6,%7,%8,%9,%10,%11,%12,%13,%14,%15,"             \
        "%16,%17,%18,%19,%20,%21,%22,%23,%24,%25,%26,%27,%28,%29,%30,%31}, [%32];" \
        : "=r"((r)[0]),"=r"((r)[1]),"=r"((r)[2]),"=r"((r)[3]),                 \
          "=r"((r)[4]),"=r"((r)[5]),"=r"((r)[6]),"=r"((r)[7]),                 \
          "=r"((r)[8]),"=r"((r)[9]),"=r"((r)[10]),"=r"((r)[11]),               \
          "=r"((r)[12]),"=r"((r)[13]),"=r"((r)[14]),"=r"((r)[15]),             \
          "=r"((r)[16]),"=r"((r)[17]),"=r"((r)[18]),"=r"((r)[19]),             \
          "=r"((r)[20]),"=r"((r)[21]),"=r"((r)[22]),"=r"((r)[23]),             \
          "=r"((r)[24]),"=r"((r)[25]),"=r"((r)[26]),"=r"((r)[27]),             \
          "=r"((r)[28]),"=r"((r)[29]),"=r"((r)[30]),"=r"((r)[31])              \
        : "r"(ta))

#define TCGEN05_ST_X16(ta, r)                                                  \
    asm volatile("tcgen05.st.sync.aligned.32x32b.x16.b32 [%0], "               \
        "{%1,%2,%3,%4,%5,%6,%7,%8,%9,%10,%11,%12,%13,%14,%15,%16};"           \
        :: "r"(ta),                                                            \
           "r"((r)[0]),"r"((r)[1]),"r"((r)[2]),"r"((r)[3]),                    \
           "r"((r)[4]),"r"((r)[5]),"r"((r)[6]),"r"((r)[7]),                    \
           "r"((r)[8]),"r"((r)[9]),"r"((r)[10]),"r"((r)[11]),                  \
           "r"((r)[12]),"r"((r)[13]),"r"((r)[14]),"r"((r)[15]) : "memory")

#if HAS_TCGEN05
__device__ __forceinline__ uint64_t make_desc(uint32_t addr) {
    const uint64_t base = (uint64_t(2) << 61) | (uint64_t(1) << 46) |
                          (uint64_t(64) << 32) | (uint64_t(1) << 16);
    return base | ((uint64_t)(addr >> 4) & 0x3FFF);
}
__device__ __forceinline__ void mma_f16_ss(uint32_t d, uint64_t a, uint64_t b,
                                           uint32_t idesc, uint32_t en) {
    asm volatile(
        "{ .reg .pred p; setp.ne.u32 p, %4, 0;\n\t"
        "tcgen05.mma.cta_group::1.kind::f16 [%0], %1, %2, %3, {%5,%5,%5,%5}, p; }"
        :: "r"(d), "l"(a), "l"(b), "r"(idesc), "r"(en), "r"(0u) : "memory");
}
__device__ __forceinline__ void mma_f16_ts(uint32_t d, uint32_t a, uint64_t b,
                                           uint32_t idesc, uint32_t en) {
    asm volatile(
        "{ .reg .pred p; setp.ne.u32 p, %4, 0;\n\t"
        "tcgen05.mma.cta_group::1.kind::f16 [%0], [%1], %2, %3, {%5,%5,%5,%5}, p; }"
        :: "r"(d), "r"(a), "l"(b), "r"(idesc), "r"(en), "r"(0u) : "memory");
}
#endif

__device__ __forceinline__ uint32_t pack_bf2(float a, float b) {
    __nv_bfloat162 t = __floats2bfloat162_rn(a, b);
    return *(uint32_t*)&t;
}

// ---------------------------------------------------------------------------
// GEMM config: SS, KC=64, SW128, bulk-B; A prefetch distance 2.
// ---------------------------------------------------------------------------
#define GEMM_MT 128
#define GEMM_NT 256
#define GEMM_IDESC ((1u<<4)|(1u<<7)|(1u<<10)|((GEMM_NT/8)<<17)|((GEMM_MT/16)<<24))
#define GEMM_BUF_BYTES 98304
#define GEMM_SMEM_BYTES (1024 + 2 * GEMM_BUF_BYTES)

struct QKVParams {
    const float* A[3];
    const __nv_bfloat16* Wh[3];
    const __nv_bfloat16* Wl[3];
    const float* bias[3];
    float* outV;
    __nv_bfloat16* outH[2];
    __nv_bfloat16* outL[2];
};

#if HAS_TCGEN05
__device__ __forceinline__ void ld_regs_a32(const float* __restrict__ A,
                                            int m0, int k0, float4 (*r)[2],
                                            int tid) {
#pragma unroll
    for (int g = 0; g < 4; g++) {
        int idx = tid + g * 256;
        int row = idx >> 3, seg = idx & 7;
        const float4* p =
            (const float4*)(A + (size_t)(m0 + row) * NE + k0 + seg * 8);
        r[g][0] = p[0];
        r[g][1] = p[1];
    }
}
__device__ __forceinline__ void st_regs_a32(char* sh, char* sl,
                                            float4 (*r)[2], int tid) {
#pragma unroll
    for (int g = 0; g < 4; g++) {
        int idx = tid + g * 256;
        int row = idx >> 3, seg = idx & 7;
        uint32_t off = (uint32_t)(row * 128 + seg * 16);
        off ^= (off >> 3) & 0x70;
        float f[8] = {r[g][0].x, r[g][0].y, r[g][0].z, r[g][0].w,
                      r[g][1].x, r[g][1].y, r[g][1].z, r[g][1].w};
        float rr[8];
        uint4 h, l;
        uint32_t* hp = &h.x;
        uint32_t* lp = &l.x;
#pragma unroll
        for (int e = 0; e < 8; e++) {
            __nv_bfloat16 hb = __float2bfloat16(f[e]);
            rr[e] = f[e] - __bfloat162float(hb);
        }
#pragma unroll
        for (int p2 = 0; p2 < 4; p2++) {
            hp[p2] = pack_bf2(f[p2 * 2], f[p2 * 2 + 1]);
            lp[p2] = pack_bf2(rr[p2 * 2], rr[p2 * 2 + 1]);
        }
        *(uint4*)(sh + off) = h;
        *(uint4*)(sl + off) = l;
    }
}
__device__ __forceinline__ void gemm_issue(uint32_t tmem, uint32_t ba,
                                           int first, uint32_t mbar) {
    FENCE_ASYNC();
    uint64_t dah = make_desc(ba);
    uint64_t dal = make_desc(ba + 16384);
    uint64_t dbh = make_desc(ba + 32768);
    uint64_t dbl = make_desc(ba + 65536);
#pragma unroll
    for (int s = 0; s < 4; s++) {
        uint64_t o2 = 2u * s;
        mma_f16_ss(tmem, dah + o2, dbh + o2, GEMM_IDESC,
                   (!first || s > 0) ? 1u : 0u);
        mma_f16_ss(tmem, dal + o2, dbh + o2, GEMM_IDESC, 1u);
        mma_f16_ss(tmem, dah + o2, dbl + o2, GEMM_IDESC, 1u);
    }
    TCGEN05_COMMIT(mbar);
}
__device__ __forceinline__ void bulk_b(uint32_t dst, uint32_t mbar,
                                       const __nv_bfloat16* Bh,
                                       const __nv_bfloat16* Bl,
                                       int by, int c) {
    const size_t toff = (size_t)(by * 16 + c) * 16384;
    MBARRIER_EXPECT_TX(mbar, 65536);
    CP_BULK(dst + 32768, (const void*)(Bh + toff), 32768, mbar);
    CP_BULK(dst + 65536, (const void*)(Bl + toff), 32768, mbar);
}
#endif

// ---------------------------------------------------------------------------
// Fused QKV projection GEMM: grid (64, 4, 3), 256 threads.
// A prefetched 2 chunks ahead (two register sets). TMEM alloc 256.
// ---------------------------------------------------------------------------
__global__ __launch_bounds__(256) void gemm_qkv_kernel(QKVParams P)
{
#if HAS_TCGEN05
    extern __shared__ __align__(1024) char smem[];
    const uint32_t sb = smem_u32(smem);
    const int tid = threadIdx.x;
    const int wid = tid >> 5, lid = tid & 31;
    const int m0 = blockIdx.x * GEMM_MT;
    const int by = blockIdx.y;
    const int n0 = by * GEMM_NT;
    const int z = blockIdx.z;
    const float* A = P.A[z];
    const __nv_bfloat16* Bh = P.Wh[z];
    const __nv_bfloat16* Bl = P.Wl[z];
    const float* bias = P.bias[z];

    if (wid == 0) TCGEN05_ALLOC(sb, 256);
    if (tid == 0) {
        MBARRIER_INIT(sb + 16, 1); MBARRIER_INIT(sb + 24, 1);
        MBARRIER_INIT(sb + 32, 1); MBARRIER_INIT(sb + 40, 1);
    }
    __syncthreads();
    uint32_t tmem;
    asm volatile("ld.shared.b32 %0, [%1];" : "=r"(tmem) : "r"(sb));

    if (wid == 0 && elect_one()) {
        bulk_b(sb + 1024, sb + 32, Bh, Bl, by, 0);
        bulk_b(sb + 1024 + GEMM_BUF_BYTES, sb + 40, Bh, Bl, by, 1);
    }
    // A prefetch distance 2: two register sets
    float4 rA[2][4][2];
    ld_regs_a32(A, m0, 0, rA[0], tid);
    ld_regs_a32(A, m0, 64, rA[1], tid);

    int ph0 = 0, ph1 = 0, pht0 = 0, pht1 = 0;
    for (int c = 0; c < 16; c++) {
        const int buf = c & 1;
        char* bs = smem + 1024 + buf * GEMM_BUF_BYTES;
        if (c >= 2) {
            if (buf == 0) { MBARRIER_WAIT_PARITY(sb + 16, ph0); ph0 ^= 1; }
            else          { MBARRIER_WAIT_PARITY(sb + 24, ph1); ph1 ^= 1; }
            if (wid == 0 && elect_one())
                bulk_b(sb + 1024 + buf * GEMM_BUF_BYTES,
                       sb + 32 + buf * 8, Bh, Bl, by, c);
        }
        st_regs_a32(bs, bs + 16384, rA[buf], tid);
        __syncthreads();
        if (wid == 0 && elect_one()) {
            if (buf == 0) { MBARRIER_WAIT_PARITY(sb + 32, pht0); pht0 ^= 1; }
            else          { MBARRIER_WAIT_PARITY(sb + 40, pht1); pht1 ^= 1; }
            gemm_issue(tmem, sb + 1024 + buf * GEMM_BUF_BYTES, c == 0,
                       sb + 16 + buf * 8);
        }
        // refill the set just consumed with chunk c+2 (full iteration to land)
        if (c + 2 < 16) ld_regs_a32(A, m0, (c + 2) * 64, rA[buf], tid);
    }
    MBARRIER_WAIT_PARITY(sb + 16, ph0);
    MBARRIER_WAIT_PARITY(sb + 24, ph1);
    TCGEN05_FENCE_AFTER();

    const int m = m0 + 32 * (wid & 3) + lid;
    const int b = m >> 11, s_ = m & (NS - 1);
    const int chalf = (wid >> 2) * 128;
#pragma unroll
    for (int i = 0; i < 4; i++) {
        uint32_t r[32];
        TCGEN05_LD_X32(r, tmem + chalf + i * 32);
        TCGEN05_WAIT_LD();
        const int nbase = n0 + chalf + i * 32;
        float vals[32];
        const float4* bp = (const float4*)(bias + nbase);
#pragma unroll
        for (int j4 = 0; j4 < 8; j4++) {
            float4 bb = bp[j4];
            vals[j4 * 4 + 0] = __uint_as_float(r[j4 * 4 + 0]) + bb.x;
            vals[j4 * 4 + 1] = __uint_as_float(r[j4 * 4 + 1]) + bb.y;
            vals[j4 * 4 + 2] = __uint_as_float(r[j4 * 4 + 2]) + bb.z;
            vals[j4 * 4 + 3] = __uint_as_float(r[j4 * 4 + 3]) + bb.w;
        }
        const int h = nbase >> 6, d0 = nbase & 63;
        const size_t base = ((size_t)(b * NH + h) * NS + s_) * ND + d0;
        if (z == 2) {
            float* dst = P.outV + base;
#pragma unroll
            for (int j = 0; j < 32; j += 4)
                *(float4*)(dst + j) =
                    make_float4(vals[j], vals[j+1], vals[j+2], vals[j+3]);
        } else {
#pragma unroll
            for (int c8 = 0; c8 < 4; c8++) {
                uint4 wh, wl;
                uint32_t* ph_ = &wh.x;
                uint32_t* pl_ = &wl.x;
#pragma unroll
                for (int p2 = 0; p2 < 4; p2++) {
                    float a = vals[c8 * 8 + p2 * 2];
                    float bv = vals[c8 * 8 + p2 * 2 + 1];
                    __nv_bfloat16 ha = __float2bfloat16(a);
                    __nv_bfloat16 hb = __float2bfloat16(bv);
                    ph_[p2] = pack_bf2(a, bv);
                    pl_[p2] = pack_bf2(a - __bfloat162float(ha),
                                       bv - __bfloat162float(hb));
                }
                *(uint4*)(P.outH[z] + base + c8 * 8) = wh;
                *(uint4*)(P.outL[z] + base + c8 * 8) = wl;
            }
        }
    }
    __syncthreads();
    if (wid == 0) TCGEN05_DEALLOC(tmem, 256);
#else
    (void)P;
#endif
}

// ---------------------------------------------------------------------------
// Output projection GEMM: A = ctx hi/lo (bf16, prefetch distance 2), bulk-B.
// grid (64,4), 256 threads. TMEM alloc 256.
// ---------------------------------------------------------------------------
__global__ __launch_bounds__(256) void gemm_ctx_kernel(
    const __nv_bfloat16* __restrict__ Ah, const __nv_bfloat16* __restrict__ Al,
    const __nv_bfloat16* __restrict__ Bh, const __nv_bfloat16* __restrict__ Bl,
    const float* __restrict__ bias, float* __restrict__ out)
{
#if HAS_TCGEN05
    extern __shared__ __align__(1024) char smem[];
    const uint32_t sb = smem_u32(smem);
    const int tid = threadIdx.x;
    const int wid = tid >> 5, lid = tid & 31;
    const int m0 = blockIdx.x * GEMM_MT;
    const int by = blockIdx.y;
    const int n0 = by * GEMM_NT;

    if (wid == 0) TCGEN05_ALLOC(sb, 256);
    if (tid == 0) {
        MBARRIER_INIT(sb + 16, 1); MBARRIER_INIT(sb + 24, 1);
        MBARRIER_INIT(sb + 32, 1); MBARRIER_INIT(sb + 40, 1);
    }
    __syncthreads();
    uint32_t tmem;
    asm volatile("ld.shared.b32 %0, [%1];" : "=r"(tmem) : "r"(sb));

    if (wid == 0 && elect_one()) {
        bulk_b(sb + 1024, sb + 32, Bh, Bl, by, 0);
        bulk_b(sb + 1024 + GEMM_BUF_BYTES, sb + 40, Bh, Bl, by, 1);
    }

    uint4 rAh[2][4], rAl[2][4];
    auto ldA = [&](int k0, int s) {
#pragma unroll
        for (int it = 0; it < 4; it++) {
            int idx = tid + it * 256;
            int row = idx >> 3, q = idx & 7;
            rAh[s][it] = *((const uint4*)(Ah + (size_t)(m0 + row) * NE + k0) + q);
            rAl[s][it] = *((const uint4*)(Al + (size_t)(m0 + row) * NE + k0) + q);
        }
    };
    auto stA = [&](char* sh, char* sl, int s) {
#pragma unroll
        for (int it = 0; it < 4; it++) {
            int idx = tid + it * 256;
            int row = idx >> 3, q = idx & 7;
            uint32_t off = (uint32_t)(row * 128 + q * 16);
            off ^= (off >> 3) & 0x70;
            *(uint4*)(sh + off) = rAh[s][it];
            *(uint4*)(sl + off) = rAl[s][it];
        }
    };
    ldA(0, 0);
    ldA(64, 1);

    int ph0 = 0, ph1 = 0, pht0 = 0, pht1 = 0;
    for (int c = 0; c < 16; c++) {
        const int buf = c & 1;
        char* bs = smem + 1024 + buf * GEMM_BUF_BYTES;
        if (c >= 2) {
            if (buf == 0) { MBARRIER_WAIT_PARITY(sb + 16, ph0); ph0 ^= 1; }
            else          { MBARRIER_WAIT_PARITY(sb + 24, ph1); ph1 ^= 1; }
            if (wid == 0 && elect_one())
                bulk_b(sb + 1024 + buf * GEMM_BUF_BYTES,
                       sb + 32 + buf * 8, Bh, Bl, by, c);
        }
        stA(bs, bs + 16384, buf);
        __syncthreads();
        if (wid == 0 && elect_one()) {
            if (buf == 0) { MBARRIER_WAIT_PARITY(sb + 32, pht0); pht0 ^= 1; }
            else          { MBARRIER_WAIT_PARITY(sb + 40, pht1); pht1 ^= 1; }
            gemm_issue(tmem, sb + 1024 + buf * GEMM_BUF_BYTES, c == 0,
                       sb + 16 + buf * 8);
        }
        if (c + 2 < 16) ldA((c + 2) * 64, buf);
    }
    MBARRIER_WAIT_PARITY(sb + 16, ph0);
    MBARRIER_WAIT_PARITY(sb + 24, ph1);
    TCGEN05_FENCE_AFTER();

    const int m = m0 + 32 * (wid & 3) + lid;
    const int chalf = (wid >> 2) * 128;
#pragma unroll
    for (int i = 0; i < 4; i++) {
        uint32_t r[32];
        TCGEN05_LD_X32(r, tmem + chalf + i * 32);
        TCGEN05_WAIT_LD();
        const int nbase = n0 + chalf + i * 32;
        const float4* bp = (const float4*)(bias + nbase);
        float* dst = out + ((size_t)m * NE + nbase);
#pragma unroll
        for (int j4 = 0; j4 < 8; j4++) {
            float4 bb = bp[j4];
            float4 w;
            w.x = __uint_as_float(r[j4 * 4 + 0]) + bb.x;
            w.y = __uint_as_float(r[j4 * 4 + 1]) + bb.y;
            w.z = __uint_as_float(r[j4 * 4 + 2]) + bb.z;
            w.w = __uint_as_float(r[j4 * 4 + 3]) + bb.w;
            *(float4*)(dst + j4 * 4) = w;
        }
    }
    __syncthreads();
    if (wid == 0) TCGEN05_DEALLOC(tmem, 256);
#else
    (void)Ah;(void)Al;(void)Bh;(void)Bl;(void)bias;(void)out;
#endif
}

// ---------------------------------------------------------------------------
// tcgen05 flash attention — byte-identical to R14 (proven, 834-era).
// P packed into TMEM (STTM), O-MMA TS mode, 2-stage KV, bounds(256,2).
// TMEM (256 cols): S 0-63, O 64-127, Ph 128-159, Pl 160-191.
// ---------------------------------------------------------------------------
#define AT_Q   1024
#define AT_QL  (AT_Q + 16384)
#define AT_STG (AT_QL + 16384)            // 2 stages x 32KB: Kh,Kl,Vh,Vl
#define AT_SMEM_BYTES (AT_STG + 2 * 32768)   // 99,328 B
#define AT_IDESC ((1u<<4)|(1u<<7)|(1u<<10)|((64/8)<<17)|((128/16)<<24))

__global__ __launch_bounds__(256, 2) void attn_mma_kernel(
    const __nv_bfloat16* __restrict__ qh, const __nv_bfloat16* __restrict__ ql,
    const __nv_bfloat16* __restrict__ kh, const __nv_bfloat16* __restrict__ kl,
    const __nv_bfloat16* __restrict__ vth, const __nv_bfloat16* __restrict__ vtl,
    const float* __restrict__ bias,
    __nv_bfloat16* __restrict__ ctx_h, __nv_bfloat16* __restrict__ ctx_l)
{
#if HAS_TCGEN05
    extern __shared__ __align__(1024) char smem[];
    const uint32_t sb = smem_u32(smem);
    const int tid = threadIdx.x;
    const int wid = tid >> 5, lid = tid & 31;
    const int s0 = blockIdx.x * 128;
    const int bh = blockIdx.y;

    const __nv_bfloat16* qhp = qh + ((size_t)bh * NS + s0) * ND;
    const __nv_bfloat16* qlp = ql + ((size_t)bh * NS + s0) * ND;
    const __nv_bfloat16* khp = kh + (size_t)bh * NS * ND;
    const __nv_bfloat16* klp = kl + (size_t)bh * NS * ND;
    const __nv_bfloat16* vhp = vth + (size_t)bh * ND * NS;
    const __nv_bfloat16* vlp = vtl + (size_t)bh * ND * NS;

    if (wid == 0) TCGEN05_ALLOC(sb, 256);
    if (tid == 0) { MBARRIER_INIT(sb + 16, 1); MBARRIER_INIT(sb + 24, 1); }
    __syncthreads();
    uint32_t tmem;
    asm volatile("ld.shared.b32 %0, [%1];" : "=r"(tmem) : "r"(sb));

#pragma unroll
    for (int it = 0; it < 4; it++) {
        int idx = tid + it * 256;
        int row = idx >> 3, q = idx & 7;
        uint32_t off = (uint32_t)(row * 128 + q * 16);
        off ^= (off >> 3) & 0x70;
        *(uint4*)(smem + AT_Q + off)  = *((const uint4*)(qhp + (size_t)row * ND) + q);
        *(uint4*)(smem + AT_QL + off) = *((const uint4*)(qlp + (size_t)row * ND) + q);
    }

    auto ld_kv = [&](int t, int stg) {
        char* ks = smem + AT_STG + stg * 32768;
        const __nv_bfloat16* kh_t = khp + (size_t)t * 64 * ND;
        const __nv_bfloat16* kl_t = klp + (size_t)t * 64 * ND;
        const __nv_bfloat16* vh_t = vhp + (size_t)t * 64;
        const __nv_bfloat16* vl_t = vlp + (size_t)t * 64;
#pragma unroll
        for (int it = 0; it < 2; it++) {
            int idx = tid + it * 256;
            int row = idx >> 3, q = idx & 7;
            uint32_t off = (uint32_t)(row * 128 + q * 16);
            off ^= (off >> 3) & 0x70;
            *(uint4*)(ks + off)         = *((const uint4*)(kh_t + (size_t)row * ND) + q);
            *(uint4*)(ks + 8192 + off)  = *((const uint4*)(kl_t + (size_t)row * ND) + q);
            *(uint4*)(ks + 16384 + off) = *((const uint4*)(vh_t + (size_t)row * NS) + q);
            *(uint4*)(ks + 24576 + off) = *((const uint4*)(vl_t + (size_t)row * NS) + q);
        }
    };

    const uint64_t dq_h = make_desc(sb + AT_Q);
    const uint64_t dq_l = make_desc(sb + AT_QL);

    auto issue_S = [&](int t) {
        const uint32_t ks = sb + AT_STG + (t & 1) * 32768;
        uint64_t dk_h = make_desc(ks), dk_l = make_desc(ks + 8192);
#pragma unroll
        for (int s4 = 0; s4 < 4; s4++) {
            uint64_t o2 = 2u * s4;
            mma_f16_ss(tmem, dq_h + o2, dk_h + o2, AT_IDESC, s4 > 0 ? 1u : 0u);
            mma_f16_ss(tmem, dq_l + o2, dk_h + o2, AT_IDESC, 1u);
            mma_f16_ss(tmem, dq_h + o2, dk_l + o2, AT_IDESC, 1u);
        }
    };
    auto issue_O = [&](int t) {
        const uint32_t ks = sb + AT_STG + (t & 1) * 32768;
        uint64_t dv_h = make_desc(ks + 16384), dv_l = make_desc(ks + 24576);
        const uint32_t p_h = tmem + 128, p_l = tmem + 160;
#pragma unroll
        for (int s4 = 0; s4 < 4; s4++) {
            uint64_t o2 = 2u * s4;
            uint32_t ao = s4 * 8;
            mma_f16_ts(tmem + 64, p_h + ao, dv_h + o2, AT_IDESC,
                       (t > 0 || s4 > 0) ? 1u : 0u);
            mma_f16_ts(tmem + 64, p_l + ao, dv_h + o2, AT_IDESC, 1u);
            mma_f16_ts(tmem + 64, p_h + ao, dv_l + o2, AT_IDESC, 1u);
        }
    };

    ld_kv(0, 0);
    __syncthreads();
    if (wid == 0 && elect_one()) {
        FENCE_ASYNC();
        issue_S(0);
        TCGEN05_COMMIT(sb + 16);
    }

    const int srow = (wid & 3) * 32 + lid;
    const int shf = wid >> 2;
    const uint32_t warp_off = (uint32_t)(wid & 3) << 21;
    const float* brow = bias + (size_t)(s0 + srow) * NS;
    float lsum = 0.f;
    int ph_s = 0, ph_o = 0;

    for (int t = 0; t < 32; t++) {
        float4 bb[8];
        const float4* bp = (const float4*)(brow + t * 64 + shf * 32);
#pragma unroll
        for (int i = 0; i < 8; i++) bb[i] = bp[i];

        MBARRIER_WAIT_PARITY(sb + 16, ph_s);   // S(t) done
        ph_s ^= 1;
        TCGEN05_FENCE_AFTER();

        uint32_t r[32];
        TCGEN05_LD_X32(r, tmem + shf * 32);
        TCGEN05_WAIT_LD();
        float p[32];
#pragma unroll
        for (int j4 = 0; j4 < 8; j4++) {
            float4 b4 = bb[j4];
            p[j4*4+0] = __expf(fmaf(__uint_as_float(r[j4*4+0]), 0.125f, b4.x));
            p[j4*4+1] = __expf(fmaf(__uint_as_float(r[j4*4+1]), 0.125f, b4.y));
            p[j4*4+2] = __expf(fmaf(__uint_as_float(r[j4*4+2]), 0.125f, b4.z));
            p[j4*4+3] = __expf(fmaf(__uint_as_float(r[j4*4+3]), 0.125f, b4.w));
            lsum += p[j4*4+0] + p[j4*4+1] + p[j4*4+2] + p[j4*4+3];
        }

        if (t >= 1) {                          // O(t-1) done reading P, V(t-1)
            MBARRIER_WAIT_PARITY(sb + 24, ph_o);
            ph_o ^= 1;
        }

        {
            uint32_t phh[16], pll[16];
#pragma unroll
            for (int i = 0; i < 16; i++) {
                float a = p[2 * i], c = p[2 * i + 1];
                __nv_bfloat16 ha = __float2bfloat16(a);
                __nv_bfloat16 hc = __float2bfloat16(c);
                phh[i] = pack_bf2(a, c);
                pll[i] = pack_bf2(a - __bfloat162float(ha),
                                  c - __bfloat162float(hc));
            }
            TCGEN05_ST_X16(tmem + 128 + shf * 16 + warp_off, phh);
            TCGEN05_ST_X16(tmem + 160 + shf * 16 + warp_off, pll);
            TCGEN05_WAIT_ST();
        }

        if (t + 1 < 32) ld_kv(t + 1, (t + 1) & 1);

        TCGEN05_FENCE_BEFORE();
        __syncthreads();

        if (wid == 0 && elect_one()) {
            FENCE_ASYNC();
            TCGEN05_FENCE_AFTER();
            if (t + 1 < 32) {
                issue_S(t + 1);
                TCGEN05_COMMIT(sb + 16);
            }
            issue_O(t);
            TCGEN05_COMMIT(sb + 24);
        }
    }
    MBARRIER_WAIT_PARITY(sb + 24, ph_o);       // O(31)
    TCGEN05_FENCE_AFTER();

    *(float*)(smem + AT_Q + tid * 4) = lsum;
    __syncthreads();
    const float lother = *(const float*)(smem + AT_Q + (tid ^ 128) * 4);
    const float inv = 1.f / (lsum + lother);

    const int b = bh >> 4, h = bh & 15;
    const size_t obase = ((size_t)b * NS + s0 + srow) * NE + h * ND + shf * 32;
    uint32_t r[32];
    TCGEN05_LD_X32(r, tmem + 64 + shf * 32);
    TCGEN05_WAIT_LD();
#pragma unroll
    for (int c8 = 0; c8 < 4; c8++) {
        uint4 wh, wl;
        uint32_t* phh = &wh.x;
        uint32_t* pll = &wl.x;
#pragma unroll
        for (int p2 = 0; p2 < 4; p2++) {
            float a = __uint_as_float(r[c8 * 8 + p2 * 2]) * inv;
            float c = __uint_as_float(r[c8 * 8 + p2 * 2 + 1]) * inv;
            __nv_bfloat16 ha = __float2bfloat16(a);
            __nv_bfloat16 hc = __float2bfloat16(c);
            phh[p2] = pack_bf2(a, c);
            pll[p2] = pack_bf2(a - __bfloat162float(ha),
                               c - __bfloat162float(hc));
        }
        *(uint4*)(ctx_h + obase + c8 * 8) = wh;
        *(uint4*)(ctx_l + obase + c8 * 8) = wl;
    }
    TCGEN05_FENCE_BEFORE();
    __syncthreads();
    if (wid == 0) TCGEN05_DEALLOC(tmem, 256);
#else
    (void)qh;(void)ql;(void)kh;(void)kl;(void)vth;(void)vtl;(void)bias;(void)ctx_h;(void)ctx_l;
#endif
}

// ---------------------------------------------------------------------------
// Weight transpose + split into TILED layout
// ---------------------------------------------------------------------------
__global__ __launch_bounds__(256) void transpose_split_tiled_kernel(
    const float* __restrict__ in, __nv_bfloat16* __restrict__ oh,
    __nv_bfloat16* __restrict__ ol, int C)
{
    __shared__ float t[64][65];
    const float* inz = in + (size_t)blockIdx.z * NE * C;
    const int r0 = blockIdx.x * 64, c0 = blockIdx.y * 64;
    const int tid = threadIdx.x;
#pragma unroll
    for (int it = 0; it < 16; it++) {
        int idx = tid + it * 256;
        int rr = idx >> 6, cc = idx & 63;
        t[rr][cc] = inz[(size_t)(r0 + rr) * C + c0 + cc];
    }
    __syncthreads();
#pragma unroll
    for (int it = 0; it < 16; it++) {
        int idx = tid + it * 256;
        int cc = idx >> 6, rr = idx & 63;
        float x = t[rr][cc];
        __nv_bfloat16 hi = __float2bfloat16(x);
        const int n = blockIdx.z * C + c0 + cc;
        const int k = r0 + rr;
        uint32_t off = (uint32_t)((n & 255) * 128 + (k & 63) * 2);
        off ^= (off >> 3) & 0x70;
        const size_t base = ((size_t)((n >> 8) * 16 + (k >> 6))) * 32768 + off;
        *(__nv_bfloat16*)((char*)oh + base) = hi;
        *(__nv_bfloat16*)((char*)ol + base) =
            __float2bfloat16(x - __bfloat162float(hi));
    }
}

// ---------------------------------------------------------------------------
// Plain transpose + split (V^T path)
// ---------------------------------------------------------------------------
__global__ __launch_bounds__(256) void transpose_split_kernel(
    const float* __restrict__ in, __nv_bfloat16* __restrict__ oh,
    __nv_bfloat16* __restrict__ ol, int C, int R)
{
    __shared__ float t[64][65];
    const float* inz = in + (size_t)blockIdx.z * R * C;
    const int r0 = blockIdx.x * 64, c0 = blockIdx.y * 64;
    const int tid = threadIdx.x;
#pragma unroll
    for (int it = 0; it < 16; it++) {
        int idx = tid + it * 256;
        int rr = idx >> 6, cc = idx & 63;
        t[rr][cc] = inz[(size_t)(r0 + rr) * C + c0 + cc];
    }
    __syncthreads();
#pragma unroll
    for (int it = 0; it < 16; it++) {
        int idx = tid + it * 256;
        int cc = idx >> 6, rr = idx & 63;
        float x = t[rr][cc];
        __nv_bfloat16 hi = __float2bfloat16(x);
        size_t o = (size_t)(blockIdx.z * C + c0 + cc) * R + r0 + rr;
        oh[o] = hi;
        ol[o] = __float2bfloat16(x - __bfloat162float(hi));
    }
}

// ---------------------------------------------------------------------------

extern "C" void kernel_launch(void* const* d_in, const int* in_sizes, int n_in,
                              void* d_out, int out_size)
{
    const float* query = (const float*)d_in[0];
    const float* key_  = (const float*)d_in[1];
    const float* value = (const float*)d_in[2];
    const float* abias = (const float*)d_in[3];
    const float* Wq = (const float*)d_in[4];
    const float* bq = (const float*)d_in[5];
    const float* Wk = (const float*)d_in[6];
    const float* bk = (const float*)d_in[7];
    const float* Wv = (const float*)d_in[8];
    const float* bv = (const float*)d_in[9];
    const float* Wo = (const float*)d_in[10];
    const float* bo = (const float*)d_in[11];
    float* out = (float*)d_out;

    float* vp;
    __nv_bfloat16 *qh, *ql, *kh, *kl, *vth, *vtl, *ah, *al, *wth, *wtl;
    cudaGetSymbolAddress((void**)&vp, g_v);
    cudaGetSymbolAddress((void**)&qh, g_qh);
    cudaGetSymbolAddress((void**)&ql, g_ql);
    cudaGetSymbolAddress((void**)&kh, g_kh);
    cudaGetSymbolAddress((void**)&kl, g_kl);
    cudaGetSymbolAddress((void**)&vth, g_vth);
    cudaGetSymbolAddress((void**)&vtl, g_vtl);
    cudaGetSymbolAddress((void**)&ah, g_ah);
    cudaGetSymbolAddress((void**)&al, g_al);
    cudaGetSymbolAddress((void**)&wth, g_wth);
    cudaGetSymbolAddress((void**)&wtl, g_wtl);

    cudaFuncSetAttribute(gemm_qkv_kernel,
                         cudaFuncAttributeMaxDynamicSharedMemorySize,
                         GEMM_SMEM_BYTES);
    cudaFuncSetAttribute(gemm_ctx_kernel,
                         cudaFuncAttributeMaxDynamicSharedMemorySize,
                         GEMM_SMEM_BYTES);
    cudaFuncSetAttribute(attn_mma_kernel,
                         cudaFuncAttributeMaxDynamicSharedMemorySize,
                         AT_SMEM_BYTES);

    // weight transposes into TILED layout (hi/lo)
    dim3 gw(16, 1, 16);
    transpose_split_tiled_kernel<<<gw, 256>>>(Wq, wth + 0 * NE * NE,
                                              wtl + 0 * NE * NE, ND);
    transpose_split_tiled_kernel<<<gw, 256>>>(Wk, wth + 1 * NE * NE,
                                              wtl + 1 * NE * NE, ND);
    transpose_split_tiled_kernel<<<gw, 256>>>(Wv, wth + 2 * NE * NE,
                                              wtl + 2 * NE * NE, ND);

    // fused QKV projections
    QKVParams P;
    P.A[0] = query; P.A[1] = key_; P.A[2] = value;
    P.Wh[0] = wth; P.Wh[1] = wth + NE * NE; P.Wh[2] = wth + 2 * NE * NE;
    P.Wl[0] = wtl; P.Wl[1] = wtl + NE * NE; P.Wl[2] = wtl + 2 * NE * NE;
    P.bias[0] = bq; P.bias[1] = bk; P.bias[2] = bv;
    P.outV = vp;
    P.outH[0] = qh; P.outH[1] = kh;
    P.outL[0] = ql; P.outL[1] = kl;
    gemm_qkv_kernel<<<dim3(64, 4, 3), 256, GEMM_SMEM_BYTES>>>(P);

    // V^T split for PV MMA
    transpose_split_kernel<<<dim3(32, 1, 64), 256>>>(vp, vth, vtl, ND, NS);

    // attention -> ctx bf16 hi/lo
    attn_mma_kernel<<<dim3(16, 64), 256, AT_SMEM_BYTES>>>(
        qh, ql, kh, kl, vth, vtl, abias, ah, al);

    // output projection (Wo tiled into slot 0)
    transpose_split_tiled_kernel<<<dim3(16, 16, 1), 256>>>(Wo, wth, wtl, NE);
    gemm_ctx_kernel<<<dim3(64, 4), 256, GEMM_SMEM_BYTES>>>(ah, al, wth, wtl, bo, out);
}

// round 16
// speedup vs baseline: 1.1215x; 1.1215x over previous
#include <cuda_runtime.h>
#include <cuda_bf16.h>
#include <cstdint>

#define NB 4
#define NS 2048
#define NE 1024
#define NH 16
#define ND 64

#if defined(__CUDA_ARCH__) && (defined(__CUDA_ARCH_FEAT_SM103_ALL) || \
    defined(__CUDA_ARCH_SPECIFIC__))
#define HAS_TCGEN05 1
#else
#define HAS_TCGEN05 0
#endif

// ---------------------------------------------------------------------------
// Device globals (scratch)
// ---------------------------------------------------------------------------
__device__ __align__(256) float g_v[NB * NH * NS * ND];
__device__ __align__(256) __nv_bfloat16 g_qh[NB * NH * NS * ND];
__device__ __align__(256) __nv_bfloat16 g_ql[NB * NH * NS * ND];
__device__ __align__(256) __nv_bfloat16 g_kh[NB * NH * NS * ND];
__device__ __align__(256) __nv_bfloat16 g_kl[NB * NH * NS * ND];
__device__ __align__(256) __nv_bfloat16 g_vth[NB * NH * ND * NS];
__device__ __align__(256) __nv_bfloat16 g_vtl[NB * NH * ND * NS];
__device__ __align__(256) __nv_bfloat16 g_ah[NB * NS * NE];       // ctx hi/lo
__device__ __align__(256) __nv_bfloat16 g_al[NB * NS * NE];
// weights, pre-tiled+swizzled: [z][n_block(4)][k_chunk(16)][32KB tile]
__device__ __align__(256) __nv_bfloat16 g_wth[3][NE * NE];
__device__ __align__(256) __nv_bfloat16 g_wtl[3][NE * NE];

// ---------------------------------------------------------------------------
// PTX helpers
// ---------------------------------------------------------------------------
__device__ __forceinline__ uint32_t smem_u32(const void* p) {
    uint32_t a;
    asm("{ .reg .u64 t; cvta.to.shared.u64 t, %1; cvt.u32.u64 %0, t; }"
        : "=r"(a) : "l"(p));
    return a;
}
__device__ __forceinline__ uint32_t elect_one() {
    uint32_t pred;
    asm volatile("{ .reg .pred p; elect.sync _|p, 0xFFFFFFFF; selp.b32 %0,1,0,p; }"
                 : "=r"(pred));
    return pred;
}
#define MBARRIER_INIT(addr, cnt) \
    asm volatile("mbarrier.init.shared.b64 [%0], %1;" :: "r"(addr), "r"(cnt) : "memory")
#define MBARRIER_EXPECT_TX(addr, bytes) \
    asm volatile("mbarrier.arrive.expect_tx.shared.b64 _, [%0], %1;" \
        :: "r"((uint32_t)(addr)), "r"((uint32_t)(bytes)) : "memory")
#define MBARRIER_WAIT_PARITY(addr, par) do {                                   \
    uint32_t _m = (addr), _p = (par), _d;                                      \
    asm volatile("{ .reg .pred p; mbarrier.try_wait.parity.acquire.cta.shared::cta.b64 p, [%1], %2; selp.b32 %0,1,0,p; }" \
        : "=r"(_d) : "r"(_m), "r"(_p) : "memory");                             \
    if (!_d) {                                                                 \
        asm volatile("{ .reg .pred P1; WL_%=: mbarrier.try_wait.parity.acquire.cta.shared::cta.b64 P1, [%0], %1, 0x989680; @P1 bra.uni WD_%=; bra.uni WL_%=; WD_%=: }" \
            :: "r"(_m), "r"(_p) : "memory");                                   \
    } } while (0)
#define CP_BULK(dst, src, bytes, mbar) \
    asm volatile("cp.async.bulk.shared::cluster.global.mbarrier::complete_tx::bytes [%0], [%1], %2, [%3];" \
        :: "r"((uint32_t)(dst)), "l"(src), "r"((uint32_t)(bytes)), \
           "r"((uint32_t)(mbar)) : "memory")
#define TCGEN05_ALLOC(saddr, ncols) \
    asm volatile("tcgen05.alloc.cta_group::1.sync.aligned.shared::cta.b32 [%0], %1;" \
        :: "r"((uint32_t)(saddr)), "r"((uint32_t)(ncols)) : "memory")
#define TCGEN05_DEALLOC(tmem, ncols) \
    asm volatile("tcgen05.dealloc.cta_group::1.sync.aligned.b32 %0, %1;" \
        :: "r"(tmem), "r"((uint32_t)(ncols)))
#define TCGEN05_COMMIT(mbar) \
    asm volatile("tcgen05.commit.cta_group::1.mbarrier::arrive::one.shared::cluster.b64 [%0];" \
        :: "r"((uint32_t)(mbar)) : "memory")
#define TCGEN05_WAIT_LD() asm volatile("tcgen05.wait::ld.sync.aligned;" ::: "memory")
#define TCGEN05_WAIT_ST() asm volatile("tcgen05.wait::st.sync.aligned;" ::: "memory")
#define TCGEN05_FENCE_AFTER() asm volatile("tcgen05.fence::after_thread_sync;" ::: "memory")
#define TCGEN05_FENCE_BEFORE() asm volatile("tcgen05.fence::before_thread_sync;" ::: "memory")
#define FENCE_ASYNC() asm volatile("fence.proxy.async.shared::cta;" ::: "memory")

#define TCGEN05_LD_X32(r, ta)                                                  \
    asm volatile("tcgen05.ld.sync.aligned.32x32b.x32.b32 "                     \
        "{%0,%1,%2,%3,%4,%5,%6,%7,%8,%9,%10,%11,%12,%13,%14,%15,"             \
        "%16,%17,%18,%19,%20,%21,%22,%23,%24,%25,%26,%27,%28,%29,%30,%31}, [%32];" \
        : "=r"((r)[0]),"=r"((r)[1]),"=r"((r)[2]),"=r"((r)[3]),                 \
          "=r"((r)[4]),"=r"((r)[5]),"=r"((r)[6]),"=r"((r)[7]),                 \
          "=r"((r)[8]),"=r"((r)[9]),"=r"((r)[10]),"=r"((r)[11]),               \
          "=r"((r)[12]),"=r"((r)[13]),"=r"((r)[14]),"=r"((r)[15]),             \
          "=r"((r)[16]),"=r"((r)[17]),"=r"((r)[18]),"=r"((r)[19]),             \
          "=r"((r)[20]),"=r"((r)[21]),"=r"((r)[22]),"=r"((r)[23]),             \
          "=r"((r)[24]),"=r"((r)[25]),"=r"((r)[26]),"=r"((r)[27]),             \
          "=r"((r)[28]),"=r"((r)[29]),"=r"((r)[30]),"=r"((r)[31])              \
        : "r"(ta))

#define TCGEN05_ST_X16(ta, r)                                                  \
    asm volatile("tcgen05.st.sync.aligned.32x32b.x16.b32 [%0], "               \
        "{%1,%2,%3,%4,%5,%6,%7,%8,%9,%10,%11,%12,%13,%14,%15,%16};"           \
        :: "r"(ta),                                                            \
           "r"((r)[0]),"r"((r)[1]),"r"((r)[2]),"r"((r)[3]),                    \
           "r"((r)[4]),"r"((r)[5]),"r"((r)[6]),"r"((r)[7]),                    \
           "r"((r)[8]),"r"((r)[9]),"r"((r)[10]),"r"((r)[11]),                  \
           "r"((r)[12]),"r"((r)[13]),"r"((r)[14]),"r"((r)[15]) : "memory")

#if HAS_TCGEN05
__device__ __forceinline__ uint64_t make_desc(uint32_t addr) {
    const uint64_t base = (uint64_t(2) << 61) | (uint64_t(1) << 46) |
                          (uint64_t(64) << 32) | (uint64_t(1) << 16);
    return base | ((uint64_t)(addr >> 4) & 0x3FFF);
}
__device__ __forceinline__ void mma_f16_ss(uint32_t d, uint64_t a, uint64_t b,
                                           uint32_t idesc, uint32_t en) {
    asm volatile(
        "{ .reg .pred p; setp.ne.u32 p, %4, 0;\n\t"
        "tcgen05.mma.cta_group::1.kind::f16 [%0], %1, %2, %3, {%5,%5,%5,%5}, p; }"
        :: "r"(d), "l"(a), "l"(b), "r"(idesc), "r"(en), "r"(0u) : "memory");
}
__device__ __forceinline__ void mma_f16_ts(uint32_t d, uint32_t a, uint64_t b,
                                           uint32_t idesc, uint32_t en) {
    asm volatile(
        "{ .reg .pred p; setp.ne.u32 p, %4, 0;\n\t"
        "tcgen05.mma.cta_group::1.kind::f16 [%0], [%1], %2, %3, {%5,%5,%5,%5}, p; }"
        :: "r"(d), "r"(a), "l"(b), "r"(idesc), "r"(en), "r"(0u) : "memory");
}
#endif

__device__ __forceinline__ uint32_t pack_bf2(float a, float b) {
    __nv_bfloat162 t = __floats2bfloat162_rn(a, b);
    return *(uint32_t*)&t;
}

// ---------------------------------------------------------------------------
// GEMM config (R13/R14 proven): SS, KC=64, SW128, bulk-B.
// ---------------------------------------------------------------------------
#define GEMM_MT 128
#define GEMM_NT 256
#define GEMM_IDESC ((1u<<4)|(1u<<7)|(1u<<10)|((GEMM_NT/8)<<17)|((GEMM_MT/16)<<24))
#define GEMM_BUF_BYTES 98304
#define GEMM_SMEM_BYTES (1024 + 2 * GEMM_BUF_BYTES)

struct QKVParams {
    const float* A[3];
    const __nv_bfloat16* Wh[3];
    const __nv_bfloat16* Wl[3];
    const float* bias[3];
    float* outV;
    __nv_bfloat16* outH[2];
    __nv_bfloat16* outL[2];
};

#if HAS_TCGEN05
__device__ __forceinline__ void ld_regs_a32(const float* __restrict__ A,
                                            int m0, int k0, float4 (*r)[2],
                                            int tid) {
#pragma unroll
    for (int g = 0; g < 4; g++) {
        int idx = tid + g * 256;
        int row = idx >> 3, seg = idx & 7;
        const float4* p =
            (const float4*)(A + (size_t)(m0 + row) * NE + k0 + seg * 8);
        r[g][0] = p[0];
        r[g][1] = p[1];
    }
}
__device__ __forceinline__ void st_regs_a32(char* sh, char* sl,
                                            float4 (*r)[2], int tid) {
#pragma unroll
    for (int g = 0; g < 4; g++) {
        int idx = tid + g * 256;
        int row = idx >> 3, seg = idx & 7;
        uint32_t off = (uint32_t)(row * 128 + seg * 16);
        off ^= (off >> 3) & 0x70;
        float f[8] = {r[g][0].x, r[g][0].y, r[g][0].z, r[g][0].w,
                      r[g][1].x, r[g][1].y, r[g][1].z, r[g][1].w};
        float rr[8];
        uint4 h, l;
        uint32_t* hp = &h.x;
        uint32_t* lp = &l.x;
#pragma unroll
        for (int e = 0; e < 8; e++) {
            __nv_bfloat16 hb = __float2bfloat16(f[e]);
            rr[e] = f[e] - __bfloat162float(hb);
        }
#pragma unroll
        for (int p2 = 0; p2 < 4; p2++) {
            hp[p2] = pack_bf2(f[p2 * 2], f[p2 * 2 + 1]);
            lp[p2] = pack_bf2(rr[p2 * 2], rr[p2 * 2 + 1]);
        }
        *(uint4*)(sh + off) = h;
        *(uint4*)(sl + off) = l;
    }
}
__device__ __forceinline__ void gemm_issue(uint32_t tmem, uint32_t ba,
                                           int first, uint32_t mbar) {
    FENCE_ASYNC();
    uint64_t dah = make_desc(ba);
    uint64_t dal = make_desc(ba + 16384);
    uint64_t dbh = make_desc(ba + 32768);
    uint64_t dbl = make_desc(ba + 65536);
#pragma unroll
    for (int s = 0; s < 4; s++) {
        uint64_t o2 = 2u * s;
        mma_f16_ss(tmem, dah + o2, dbh + o2, GEMM_IDESC,
                   (!first || s > 0) ? 1u : 0u);
        mma_f16_ss(tmem, dal + o2, dbh + o2, GEMM_IDESC, 1u);
        mma_f16_ss(tmem, dah + o2, dbl + o2, GEMM_IDESC, 1u);
    }
    TCGEN05_COMMIT(mbar);
}
__device__ __forceinline__ void bulk_b(uint32_t dst, uint32_t mbar,
                                       const __nv_bfloat16* Bh,
                                       const __nv_bfloat16* Bl,
                                       int by, int c) {
    const size_t toff = (size_t)(by * 16 + c) * 16384;
    MBARRIER_EXPECT_TX(mbar, 65536);
    CP_BULK(dst + 32768, (const void*)(Bh + toff), 32768, mbar);
    CP_BULK(dst + 65536, (const void*)(Bl + toff), 32768, mbar);
}
#endif

// ---------------------------------------------------------------------------
// Fused QKV projection GEMM (R14): grid (64, 4, 3), 256 threads.
// ---------------------------------------------------------------------------
__global__ __launch_bounds__(256) void gemm_qkv_kernel(QKVParams P)
{
#if HAS_TCGEN05
    extern __shared__ __align__(1024) char smem[];
    const uint32_t sb = smem_u32(smem);
    const int tid = threadIdx.x;
    const int wid = tid >> 5, lid = tid & 31;
    const int m0 = blockIdx.x * GEMM_MT;
    const int by = blockIdx.y;
    const int n0 = by * GEMM_NT;
    const int z = blockIdx.z;
    const float* A = P.A[z];
    const __nv_bfloat16* Bh = P.Wh[z];
    const __nv_bfloat16* Bl = P.Wl[z];
    const float* bias = P.bias[z];

    if (wid == 0) TCGEN05_ALLOC(sb, 512);
    if (tid == 0) {
        MBARRIER_INIT(sb + 16, 1); MBARRIER_INIT(sb + 24, 1);
        MBARRIER_INIT(sb + 32, 1); MBARRIER_INIT(sb + 40, 1);
    }
    __syncthreads();
    uint32_t tmem;
    asm volatile("ld.shared.b32 %0, [%1];" : "=r"(tmem) : "r"(sb));

    if (wid == 0 && elect_one()) {
        bulk_b(sb + 1024, sb + 32, Bh, Bl, by, 0);
        bulk_b(sb + 1024 + GEMM_BUF_BYTES, sb + 40, Bh, Bl, by, 1);
    }
    float4 rA[4][2];
    ld_regs_a32(A, m0, 0, rA, tid);

    int ph0 = 0, ph1 = 0, pht0 = 0, pht1 = 0;
    for (int c = 0; c < 16; c++) {
        const int buf = c & 1;
        char* bs = smem + 1024 + buf * GEMM_BUF_BYTES;
        if (c >= 2) {
            if (buf == 0) { MBARRIER_WAIT_PARITY(sb + 16, ph0); ph0 ^= 1; }
            else          { MBARRIER_WAIT_PARITY(sb + 24, ph1); ph1 ^= 1; }
            if (wid == 0 && elect_one())
                bulk_b(sb + 1024 + buf * GEMM_BUF_BYTES,
                       sb + 32 + buf * 8, Bh, Bl, by, c);
        }
        st_regs_a32(bs, bs + 16384, rA, tid);
        if (c < 15) ld_regs_a32(A, m0, (c + 1) * 64, rA, tid);
        __syncthreads();
        if (wid == 0 && elect_one()) {
            if (buf == 0) { MBARRIER_WAIT_PARITY(sb + 32, pht0); pht0 ^= 1; }
            else          { MBARRIER_WAIT_PARITY(sb + 40, pht1); pht1 ^= 1; }
            gemm_issue(tmem, sb + 1024 + buf * GEMM_BUF_BYTES, c == 0,
                       sb + 16 + buf * 8);
        }
    }
    MBARRIER_WAIT_PARITY(sb + 16, ph0);
    MBARRIER_WAIT_PARITY(sb + 24, ph1);
    TCGEN05_FENCE_AFTER();

    const int m = m0 + 32 * (wid & 3) + lid;
    const int b = m >> 11, s_ = m & (NS - 1);
    const int chalf = (wid >> 2) * 128;
#pragma unroll
    for (int i = 0; i < 4; i++) {
        uint32_t r[32];
        TCGEN05_LD_X32(r, tmem + chalf + i * 32);
        TCGEN05_WAIT_LD();
        const int nbase = n0 + chalf + i * 32;
        float vals[32];
        const float4* bp = (const float4*)(bias + nbase);
#pragma unroll
        for (int j4 = 0; j4 < 8; j4++) {
            float4 bb = bp[j4];
            vals[j4 * 4 + 0] = __uint_as_float(r[j4 * 4 + 0]) + bb.x;
            vals[j4 * 4 + 1] = __uint_as_float(r[j4 * 4 + 1]) + bb.y;
            vals[j4 * 4 + 2] = __uint_as_float(r[j4 * 4 + 2]) + bb.z;
            vals[j4 * 4 + 3] = __uint_as_float(r[j4 * 4 + 3]) + bb.w;
        }
        const int h = nbase >> 6, d0 = nbase & 63;
        const size_t base = ((size_t)(b * NH + h) * NS + s_) * ND + d0;
        if (z == 2) {
            float* dst = P.outV + base;
#pragma unroll
            for (int j = 0; j < 32; j += 4)
                *(float4*)(dst + j) =
                    make_float4(vals[j], vals[j+1], vals[j+2], vals[j+3]);
        } else {
#pragma unroll
            for (int c8 = 0; c8 < 4; c8++) {
                uint4 wh, wl;
                uint32_t* ph_ = &wh.x;
                uint32_t* pl_ = &wl.x;
#pragma unroll
                for (int p2 = 0; p2 < 4; p2++) {
                    float a = vals[c8 * 8 + p2 * 2];
                    float bv = vals[c8 * 8 + p2 * 2 + 1];
                    __nv_bfloat16 ha = __float2bfloat16(a);
                    __nv_bfloat16 hb = __float2bfloat16(bv);
                    ph_[p2] = pack_bf2(a, bv);
                    pl_[p2] = pack_bf2(a - __bfloat162float(ha),
                                       bv - __bfloat162float(hb));
                }
                *(uint4*)(P.outH[z] + base + c8 * 8) = wh;
                *(uint4*)(P.outL[z] + base + c8 * 8) = wl;
            }
        }
    }
    __syncthreads();
    if (wid == 0) TCGEN05_DEALLOC(tmem, 512);
#else
    (void)P;
#endif
}

// ---------------------------------------------------------------------------
// Output projection GEMM (R14): grid (64,4), 256 threads.
// ---------------------------------------------------------------------------
__global__ __launch_bounds__(256) void gemm_ctx_kernel(
    const __nv_bfloat16* __restrict__ Ah, const __nv_bfloat16* __restrict__ Al,
    const __nv_bfloat16* __restrict__ Bh, const __nv_bfloat16* __restrict__ Bl,
    const float* __restrict__ bias, float* __restrict__ out)
{
#if HAS_TCGEN05
    extern __shared__ __align__(1024) char smem[];
    const uint32_t sb = smem_u32(smem);
    const int tid = threadIdx.x;
    const int wid = tid >> 5, lid = tid & 31;
    const int m0 = blockIdx.x * GEMM_MT;
    const int by = blockIdx.y;
    const int n0 = by * GEMM_NT;

    if (wid == 0) TCGEN05_ALLOC(sb, 512);
    if (tid == 0) {
        MBARRIER_INIT(sb + 16, 1); MBARRIER_INIT(sb + 24, 1);
        MBARRIER_INIT(sb + 32, 1); MBARRIER_INIT(sb + 40, 1);
    }
    __syncthreads();
    uint32_t tmem;
    asm volatile("ld.shared.b32 %0, [%1];" : "=r"(tmem) : "r"(sb));

    if (wid == 0 && elect_one()) {
        bulk_b(sb + 1024, sb + 32, Bh, Bl, by, 0);
        bulk_b(sb + 1024 + GEMM_BUF_BYTES, sb + 40, Bh, Bl, by, 1);
    }

    uint4 rAh[4], rAl[4];
    auto ldA = [&](int k0) {
#pragma unroll
        for (int it = 0; it < 4; it++) {
            int idx = tid + it * 256;
            int row = idx >> 3, q = idx & 7;
            rAh[it] = *((const uint4*)(Ah + (size_t)(m0 + row) * NE + k0) + q);
            rAl[it] = *((const uint4*)(Al + (size_t)(m0 + row) * NE + k0) + q);
        }
    };
    auto stA = [&](char* sh, char* sl) {
#pragma unroll
        for (int it = 0; it < 4; it++) {
            int idx = tid + it * 256;
            int row = idx >> 3, q = idx & 7;
            uint32_t off = (uint32_t)(row * 128 + q * 16);
            off ^= (off >> 3) & 0x70;
            *(uint4*)(sh + off) = rAh[it];
            *(uint4*)(sl + off) = rAl[it];
        }
    };
    ldA(0);

    int ph0 = 0, ph1 = 0, pht0 = 0, pht1 = 0;
    for (int c = 0; c < 16; c++) {
        const int buf = c & 1;
        char* bs = smem + 1024 + buf * GEMM_BUF_BYTES;
        if (c >= 2) {
            if (buf == 0) { MBARRIER_WAIT_PARITY(sb + 16, ph0); ph0 ^= 1; }
            else          { MBARRIER_WAIT_PARITY(sb + 24, ph1); ph1 ^= 1; }
            if (wid == 0 && elect_one())
                bulk_b(sb + 1024 + buf * GEMM_BUF_BYTES,
                       sb + 32 + buf * 8, Bh, Bl, by, c);
        }
        stA(bs, bs + 16384);
        if (c < 15) ldA((c + 1) * 64);
        __syncthreads();
        if (wid == 0 && elect_one()) {
            if (buf == 0) { MBARRIER_WAIT_PARITY(sb + 32, pht0); pht0 ^= 1; }
            else          { MBARRIER_WAIT_PARITY(sb + 40, pht1); pht1 ^= 1; }
            gemm_issue(tmem, sb + 1024 + buf * GEMM_BUF_BYTES, c == 0,
                       sb + 16 + buf * 8);
        }
    }
    MBARRIER_WAIT_PARITY(sb + 16, ph0);
    MBARRIER_WAIT_PARITY(sb + 24, ph1);
    TCGEN05_FENCE_AFTER();

    const int m = m0 + 32 * (wid & 3) + lid;
    const int chalf = (wid >> 2) * 128;
#pragma unroll
    for (int i = 0; i < 4; i++) {
        uint32_t r[32];
        TCGEN05_LD_X32(r, tmem + chalf + i * 32);
        TCGEN05_WAIT_LD();
        const int nbase = n0 + chalf + i * 32;
        const float4* bp = (const float4*)(bias + nbase);
        float* dst = out + ((size_t)m * NE + nbase);
#pragma unroll
        for (int j4 = 0; j4 < 8; j4++) {
            float4 bb = bp[j4];
            float4 w;
            w.x = __uint_as_float(r[j4 * 4 + 0]) + bb.x;
            w.y = __uint_as_float(r[j4 * 4 + 1]) + bb.y;
            w.z = __uint_as_float(r[j4 * 4 + 2]) + bb.z;
            w.w = __uint_as_float(r[j4 * 4 + 3]) + bb.w;
            *(float4*)(dst + j4 * 4) = w;
        }
    }
    __syncthreads();
    if (wid == 0) TCGEN05_DEALLOC(tmem, 512);
#else
    (void)Ah;(void)Al;(void)Bh;(void)Bl;(void)bias;(void)out;
#endif
}

// ---------------------------------------------------------------------------
// tcgen05 flash attention (R14): P packed into TMEM (STTM), O-MMA TS mode,
// 2-stage KV, bounds(256,2).
// TMEM (256 cols): S 0-63, O 64-127, Ph 128-159, Pl 160-191.
// ---------------------------------------------------------------------------
#define AT_Q   1024
#define AT_QL  (AT_Q + 16384)
#define AT_STG (AT_QL + 16384)            // 2 stages x 32KB: Kh,Kl,Vh,Vl
#define AT_SMEM_BYTES (AT_STG + 2 * 32768)   // 99,328 B
#define AT_IDESC ((1u<<4)|(1u<<7)|(1u<<10)|((64/8)<<17)|((128/16)<<24))

__global__ __launch_bounds__(256, 2) void attn_mma_kernel(
    const __nv_bfloat16* __restrict__ qh, const __nv_bfloat16* __restrict__ ql,
    const __nv_bfloat16* __restrict__ kh, const __nv_bfloat16* __restrict__ kl,
    const __nv_bfloat16* __restrict__ vth, const __nv_bfloat16* __restrict__ vtl,
    const float* __restrict__ bias,
    __nv_bfloat16* __restrict__ ctx_h, __nv_bfloat16* __restrict__ ctx_l)
{
#if HAS_TCGEN05
    extern __shared__ __align__(1024) char smem[];
    const uint32_t sb = smem_u32(smem);
    const int tid = threadIdx.x;
    const int wid = tid >> 5, lid = tid & 31;
    const int s0 = blockIdx.x * 128;
    const int bh = blockIdx.y;

    const __nv_bfloat16* qhp = qh + ((size_t)bh * NS + s0) * ND;
    const __nv_bfloat16* qlp = ql + ((size_t)bh * NS + s0) * ND;
    const __nv_bfloat16* khp = kh + (size_t)bh * NS * ND;
    const __nv_bfloat16* klp = kl + (size_t)bh * NS * ND;
    const __nv_bfloat16* vhp = vth + (size_t)bh * ND * NS;
    const __nv_bfloat16* vlp = vtl + (size_t)bh * ND * NS;

    if (wid == 0) TCGEN05_ALLOC(sb, 256);
    if (tid == 0) { MBARRIER_INIT(sb + 16, 1); MBARRIER_INIT(sb + 24, 1); }
    __syncthreads();
    uint32_t tmem;
    asm volatile("ld.shared.b32 %0, [%1];" : "=r"(tmem) : "r"(sb));

#pragma unroll
    for (int it = 0; it < 4; it++) {
        int idx = tid + it * 256;
        int row = idx >> 3, q = idx & 7;
        uint32_t off = (uint32_t)(row * 128 + q * 16);
        off ^= (off >> 3) & 0x70;
        *(uint4*)(smem + AT_Q + off)  = *((const uint4*)(qhp + (size_t)row * ND) + q);
        *(uint4*)(smem + AT_QL + off) = *((const uint4*)(qlp + (size_t)row * ND) + q);
    }

    auto ld_kv = [&](int t, int stg) {
        char* ks = smem + AT_STG + stg * 32768;
        const __nv_bfloat16* kh_t = khp + (size_t)t * 64 * ND;
        const __nv_bfloat16* kl_t = klp + (size_t)t * 64 * ND;
        const __nv_bfloat16* vh_t = vhp + (size_t)t * 64;
        const __nv_bfloat16* vl_t = vlp + (size_t)t * 64;
#pragma unroll
        for (int it = 0; it < 2; it++) {
            int idx = tid + it * 256;
            int row = idx >> 3, q = idx & 7;
            uint32_t off = (uint32_t)(row * 128 + q * 16);
            off ^= (off >> 3) & 0x70;
            *(uint4*)(ks + off)         = *((const uint4*)(kh_t + (size_t)row * ND) + q);
            *(uint4*)(ks + 8192 + off)  = *((const uint4*)(kl_t + (size_t)row * ND) + q);
            *(uint4*)(ks + 16384 + off) = *((const uint4*)(vh_t + (size_t)row * NS) + q);
            *(uint4*)(ks + 24576 + off) = *((const uint4*)(vl_t + (size_t)row * NS) + q);
        }
    };

    const uint64_t dq_h = make_desc(sb + AT_Q);
    const uint64_t dq_l = make_desc(sb + AT_QL);

    auto issue_S = [&](int t) {
        const uint32_t ks = sb + AT_STG + (t & 1) * 32768;
        uint64_t dk_h = make_desc(ks), dk_l = make_desc(ks + 8192);
#pragma unroll
        for (int s4 = 0; s4 < 4; s4++) {
            uint64_t o2 = 2u * s4;
            mma_f16_ss(tmem, dq_h + o2, dk_h + o2, AT_IDESC, s4 > 0 ? 1u : 0u);
            mma_f16_ss(tmem, dq_l + o2, dk_h + o2, AT_IDESC, 1u);
            mma_f16_ss(tmem, dq_h + o2, dk_l + o2, AT_IDESC, 1u);
        }
    };
    auto issue_O = [&](int t) {
        const uint32_t ks = sb + AT_STG + (t & 1) * 32768;
        uint64_t dv_h = make_desc(ks + 16384), dv_l = make_desc(ks + 24576);
        const uint32_t p_h = tmem + 128, p_l = tmem + 160;
#pragma unroll
        for (int s4 = 0; s4 < 4; s4++) {
            uint64_t o2 = 2u * s4;
            uint32_t ao = s4 * 8;
            mma_f16_ts(tmem + 64, p_h + ao, dv_h + o2, AT_IDESC,
                       (t > 0 || s4 > 0) ? 1u : 0u);
            mma_f16_ts(tmem + 64, p_l + ao, dv_h + o2, AT_IDESC, 1u);
            mma_f16_ts(tmem + 64, p_h + ao, dv_l + o2, AT_IDESC, 1u);
        }
    };

    ld_kv(0, 0);
    __syncthreads();
    if (wid == 0 && elect_one()) {
        FENCE_ASYNC();
        issue_S(0);
        TCGEN05_COMMIT(sb + 16);
    }

    const int srow = (wid & 3) * 32 + lid;
    const int shf = wid >> 2;
    const uint32_t warp_off = (uint32_t)(wid & 3) << 21;
    const float* brow = bias + (size_t)(s0 + srow) * NS;
    float lsum = 0.f;
    int ph_s = 0, ph_o = 0;

    for (int t = 0; t < 32; t++) {
        float4 bb[8];
        const float4* bp = (const float4*)(brow + t * 64 + shf * 32);
#pragma unroll
        for (int i = 0; i < 8; i++) bb[i] = bp[i];

        MBARRIER_WAIT_PARITY(sb + 16, ph_s);   // S(t) done
        ph_s ^= 1;
        TCGEN05_FENCE_AFTER();

        uint32_t r[32];
        TCGEN05_LD_X32(r, tmem + shf * 32);
        TCGEN05_WAIT_LD();
        float p[32];
#pragma unroll
        for (int j4 = 0; j4 < 8; j4++) {
            float4 b4 = bb[j4];
            p[j4*4+0] = __expf(fmaf(__uint_as_float(r[j4*4+0]), 0.125f, b4.x));
            p[j4*4+1] = __expf(fmaf(__uint_as_float(r[j4*4+1]), 0.125f, b4.y));
            p[j4*4+2] = __expf(fmaf(__uint_as_float(r[j4*4+2]), 0.125f, b4.z));
            p[j4*4+3] = __expf(fmaf(__uint_as_float(r[j4*4+3]), 0.125f, b4.w));
            lsum += p[j4*4+0] + p[j4*4+1] + p[j4*4+2] + p[j4*4+3];
        }

        if (t >= 1) {                          // O(t-1) done reading P, V(t-1)
            MBARRIER_WAIT_PARITY(sb + 24, ph_o);
            ph_o ^= 1;
        }

        {
            uint32_t phh[16], pll[16];
#pragma unroll
            for (int i = 0; i < 16; i++) {
                float a = p[2 * i], c = p[2 * i + 1];
                __nv_bfloat16 ha = __float2bfloat16(a);
                __nv_bfloat16 hc = __float2bfloat16(c);
                phh[i] = pack_bf2(a, c);
                pll[i] = pack_bf2(a - __bfloat162float(ha),
                                  c - __bfloat162float(hc));
            }
            TCGEN05_ST_X16(tmem + 128 + shf * 16 + warp_off, phh);
            TCGEN05_ST_X16(tmem + 160 + shf * 16 + warp_off, pll);
            TCGEN05_WAIT_ST();
        }

        if (t + 1 < 32) ld_kv(t + 1, (t + 1) & 1);

        TCGEN05_FENCE_BEFORE();
        __syncthreads();

        if (wid == 0 && elect_one()) {
            FENCE_ASYNC();
            TCGEN05_FENCE_AFTER();
            if (t + 1 < 32) {
                issue_S(t + 1);
                TCGEN05_COMMIT(sb + 16);
            }
            issue_O(t);
            TCGEN05_COMMIT(sb + 24);
        }
    }
    MBARRIER_WAIT_PARITY(sb + 24, ph_o);       // O(31)
    TCGEN05_FENCE_AFTER();

    *(float*)(smem + AT_Q + tid * 4) = lsum;
    __syncthreads();
    const float lother = *(const float*)(smem + AT_Q + (tid ^ 128) * 4);
    const float inv = 1.f / (lsum + lother);

    const int b = bh >> 4, h = bh & 15;
    const size_t obase = ((size_t)b * NS + s0 + srow) * NE + h * ND + shf * 32;
    uint32_t r[32];
    TCGEN05_LD_X32(r, tmem + 64 + shf * 32);
    TCGEN05_WAIT_LD();
#pragma unroll
    for (int c8 = 0; c8 < 4; c8++) {
        uint4 wh, wl;
        uint32_t* phh = &wh.x;
        uint32_t* pll = &wl.x;
#pragma unroll
        for (int p2 = 0; p2 < 4; p2++) {
            float a = __uint_as_float(r[c8 * 8 + p2 * 2]) * inv;
            float c = __uint_as_float(r[c8 * 8 + p2 * 2 + 1]) * inv;
            __nv_bfloat16 ha = __float2bfloat16(a);
            __nv_bfloat16 hc = __float2bfloat16(c);
            phh[p2] = pack_bf2(a, c);
            pll[p2] = pack_bf2(a - __bfloat162float(ha),
                               c - __bfloat162float(hc));
        }
        *(uint4*)(ctx_h + obase + c8 * 8) = wh;
        *(uint4*)(ctx_l + obase + c8 * 8) = wl;
    }
    TCGEN05_FENCE_BEFORE();
    __syncthreads();
    if (wid == 0) TCGEN05_DEALLOC(tmem, 256);
#else
    (void)qh;(void)ql;(void)kh;(void)kl;(void)vth;(void)vtl;(void)bias;(void)ctx_h;(void)ctx_l;
#endif
}

// ---------------------------------------------------------------------------
// Weight transpose + split into TILED layout
// ---------------------------------------------------------------------------
__global__ __launch_bounds__(256) void transpose_split_tiled_kernel(
    const float* __restrict__ in, __nv_bfloat16* __restrict__ oh,
    __nv_bfloat16* __restrict__ ol, int C)
{
    __shared__ float t[64][65];
    const float* inz = in + (size_t)blockIdx.z * NE * C;
    const int r0 = blockIdx.x * 64, c0 = blockIdx.y * 64;
    const int tid = threadIdx.x;
#pragma unroll
    for (int it = 0; it < 16; it++) {
        int idx = tid + it * 256;
        int rr = idx >> 6, cc = idx & 63;
        t[rr][cc] = inz[(size_t)(r0 + rr) * C + c0 + cc];
    }
    __syncthreads();
#pragma unroll
    for (int it = 0; it < 16; it++) {
        int idx = tid + it * 256;
        int cc = idx >> 6, rr = idx & 63;
        float x = t[rr][cc];
        __nv_bfloat16 hi = __float2bfloat16(x);
        const int n = blockIdx.z * C + c0 + cc;
        const int k = r0 + rr;
        uint32_t off = (uint32_t)((n & 255) * 128 + (k & 63) * 2);
        off ^= (off >> 3) & 0x70;
        const size_t base = ((size_t)((n >> 8) * 16 + (k >> 6))) * 32768 + off;
        *(__nv_bfloat16*)((char*)oh + base) = hi;
        *(__nv_bfloat16*)((char*)ol + base) =
            __float2bfloat16(x - __bfloat162float(hi));
    }
}

// ---------------------------------------------------------------------------
// Plain transpose + split (V^T path)
// ---------------------------------------------------------------------------
__global__ __launch_bounds__(256) void transpose_split_kernel(
    const float* __restrict__ in, __nv_bfloat16* __restrict__ oh,
    __nv_bfloat16* __restrict__ ol, int C, int R)
{
    __shared__ float t[64][65];
    const float* inz = in + (size_t)blockIdx.z * R * C;
    const int r0 = blockIdx.x * 64, c0 = blockIdx.y * 64;
    const int tid = threadIdx.x;
#pragma unroll
    for (int it = 0; it < 16; it++) {
        int idx = tid + it * 256;
        int rr = idx >> 6, cc = idx & 63;
        t[rr][cc] = inz[(size_t)(r0 + rr) * C + c0 + cc];
    }
    __syncthreads();
#pragma unroll
    for (int it = 0; it < 16; it++) {
        int idx = tid + it * 256;
        int cc = idx >> 6, rr = idx & 63;
        float x = t[rr][cc];
        __nv_bfloat16 hi = __float2bfloat16(x);
        size_t o = (size_t)(blockIdx.z * C + c0 + cc) * R + r0 + rr;
        oh[o] = hi;
        ol[o] = __float2bfloat16(x - __bfloat162float(hi));
    }
}

// ---------------------------------------------------------------------------

extern "C" void kernel_launch(void* const* d_in, const int* in_sizes, int n_in,
                              void* d_out, int out_size)
{
    const float* query = (const float*)d_in[0];
    const float* key_  = (const float*)d_in[1];
    const float* value = (const float*)d_in[2];
    const float* abias = (const float*)d_in[3];
    const float* Wq = (const float*)d_in[4];
    const float* bq = (const float*)d_in[5];
    const float* Wk = (const float*)d_in[6];
    const float* bk = (const float*)d_in[7];
    const float* Wv = (const float*)d_in[8];
    const float* bv = (const float*)d_in[9];
    const float* Wo = (const float*)d_in[10];
    const float* bo = (const float*)d_in[11];
    float* out = (float*)d_out;

    float* vp;
    __nv_bfloat16 *qh, *ql, *kh, *kl, *vth, *vtl, *ah, *al, *wth, *wtl;
    cudaGetSymbolAddress((void**)&vp, g_v);
    cudaGetSymbolAddress((void**)&qh, g_qh);
    cudaGetSymbolAddress((void**)&ql, g_ql);
    cudaGetSymbolAddress((void**)&kh, g_kh);
    cudaGetSymbolAddress((void**)&kl, g_kl);
    cudaGetSymbolAddress((void**)&vth, g_vth);
    cudaGetSymbolAddress((void**)&vtl, g_vtl);
    cudaGetSymbolAddress((void**)&ah, g_ah);
    cudaGetSymbolAddress((void**)&al, g_al);
    cudaGetSymbolAddress((void**)&wth, g_wth);
    cudaGetSymbolAddress((void**)&wtl, g_wtl);

    cudaFuncSetAttribute(gemm_qkv_kernel,
                         cudaFuncAttributeMaxDynamicSharedMemorySize,
                         GEMM_SMEM_BYTES);
    cudaFuncSetAttribute(gemm_ctx_kernel,
                         cudaFuncAttributeMaxDynamicSharedMemorySize,
                         GEMM_SMEM_BYTES);
    cudaFuncSetAttribute(attn_mma_kernel,
                         cudaFuncAttributeMaxDynamicSharedMemorySize,
                         AT_SMEM_BYTES);

    // weight transposes into TILED layout (hi/lo)
    dim3 gw(16, 1, 16);
    transpose_split_tiled_kernel<<<gw, 256>>>(Wq, wth + 0 * NE * NE,
                                              wtl + 0 * NE * NE, ND);
    transpose_split_tiled_kernel<<<gw, 256>>>(Wk, wth + 1 * NE * NE,
                                              wtl + 1 * NE * NE, ND);
    transpose_split_tiled_kernel<<<gw, 256>>>(Wv, wth + 2 * NE * NE,
                                              wtl + 2 * NE * NE, ND);

    // fused QKV projections
    QKVParams P;
    P.A[0] = query; P.A[1] = key_; P.A[2] = value;
    P.Wh[0] = wth; P.Wh[1] = wth + NE * NE; P.Wh[2] = wth + 2 * NE * NE;
    P.Wl[0] = wtl; P.Wl[1] = wtl + NE * NE; P.Wl[2] = wtl + 2 * NE * NE;
    P.bias[0] = bq; P.bias[1] = bk; P.bias[2] = bv;
    P.outV = vp;
    P.outH[0] = qh; P.outH[1] = kh;
    P.outL[0] = ql; P.outL[1] = kl;
    gemm_qkv_kernel<<<dim3(64, 4, 3), 256, GEMM_SMEM_BYTES>>>(P);

    // V^T split for PV MMA
    transpose_split_kernel<<<dim3(32, 1, 64), 256>>>(vp, vth, vtl, ND, NS);

    // attention -> ctx bf16 hi/lo
    attn_mma_kernel<<<dim3(16, 64), 256, AT_SMEM_BYTES>>>(
        qh, ql, kh, kl, vth, vtl, abias, ah, al);

    // output projection (Wo tiled into slot 0)
    transpose_split_tiled_kernel<<<dim3(16, 16, 1), 256>>>(Wo, wth, wtl, NE);
    gemm_ctx_kernel<<<dim3(64, 4), 256, GEMM_SMEM_BYTES>>>(ah, al, wth, wtl, bo, out);
}

// round 17
// speedup vs baseline: 1.1316x; 1.0090x over previous
#include <cuda_runtime.h>
#include <cuda_bf16.h>
#include <cstdint>

#define NB 4
#define NS 2048
#define NE 1024
#define NH 16
#define ND 64

#if defined(__CUDA_ARCH__) && (defined(__CUDA_ARCH_FEAT_SM103_ALL) || \
    defined(__CUDA_ARCH_SPECIFIC__))
#define HAS_TCGEN05 1
#else
#define HAS_TCGEN05 0
#endif

// ---------------------------------------------------------------------------
// Device globals (scratch)
// ---------------------------------------------------------------------------
__device__ __align__(256) __nv_bfloat16 g_qh[NB * NH * NS * ND];
__device__ __align__(256) __nv_bfloat16 g_ql[NB * NH * NS * ND];
__device__ __align__(256) __nv_bfloat16 g_kh[NB * NH * NS * ND];
__device__ __align__(256) __nv_bfloat16 g_kl[NB * NH * NS * ND];
__device__ __align__(256) __nv_bfloat16 g_vth[NB * NH * ND * NS];  // V^T [bh][d][s]
__device__ __align__(256) __nv_bfloat16 g_vtl[NB * NH * ND * NS];
__device__ __align__(256) __nv_bfloat16 g_ah[NB * NS * NE];        // ctx hi/lo
__device__ __align__(256) __nv_bfloat16 g_al[NB * NS * NE];
// weights, pre-tiled+swizzled: [z][n_block(4)][k_chunk(16)][32KB tile]
__device__ __align__(256) __nv_bfloat16 g_wth[3][NE * NE];
__device__ __align__(256) __nv_bfloat16 g_wtl[3][NE * NE];

// ---------------------------------------------------------------------------
// PTX helpers
// ---------------------------------------------------------------------------
__device__ __forceinline__ uint32_t smem_u32(const void* p) {
    uint32_t a;
    asm("{ .reg .u64 t; cvta.to.shared.u64 t, %1; cvt.u32.u64 %0, t; }"
        : "=r"(a) : "l"(p));
    return a;
}
__device__ __forceinline__ uint32_t elect_one() {
    uint32_t pred;
    asm volatile("{ .reg .pred p; elect.sync _|p, 0xFFFFFFFF; selp.b32 %0,1,0,p; }"
                 : "=r"(pred));
    return pred;
}
#define MBARRIER_INIT(addr, cnt) \
    asm volatile("mbarrier.init.shared.b64 [%0], %1;" :: "r"(addr), "r"(cnt) : "memory")
#define MBARRIER_EXPECT_TX(addr, bytes) \
    asm volatile("mbarrier.arrive.expect_tx.shared.b64 _, [%0], %1;" \
        :: "r"((uint32_t)(addr)), "r"((uint32_t)(bytes)) : "memory")
#define MBARRIER_WAIT_PARITY(addr, par) do {                                   \
    uint32_t _m = (addr), _p = (par), _d;                                      \
    asm volatile("{ .reg .pred p; mbarrier.try_wait.parity.acquire.cta.shared::cta.b64 p, [%1], %2; selp.b32 %0,1,0,p; }" \
        : "=r"(_d) : "r"(_m), "r"(_p) : "memory");                             \
    if (!_d) {                                                                 \
        asm volatile("{ .reg .pred P1; WL_%=: mbarrier.try_wait.parity.acquire.cta.shared::cta.b64 P1, [%0], %1, 0x989680; @P1 bra.uni WD_%=; bra.uni WL_%=; WD_%=: }" \
            :: "r"(_m), "r"(_p) : "memory");                                   \
    } } while (0)
#define CP_BULK(dst, src, bytes, mbar) \
    asm volatile("cp.async.bulk.shared::cluster.global.mbarrier::complete_tx::bytes [%0], [%1], %2, [%3];" \
        :: "r"((uint32_t)(dst)), "l"(src), "r"((uint32_t)(bytes)), \
           "r"((uint32_t)(mbar)) : "memory")
#define TCGEN05_ALLOC(saddr, ncols) \
    asm volatile("tcgen05.alloc.cta_group::1.sync.aligned.shared::cta.b32 [%0], %1;" \
        :: "r"((uint32_t)(saddr)), "r"((uint32_t)(ncols)) : "memory")
#define TCGEN05_DEALLOC(tmem, ncols) \
    asm volatile("tcgen05.dealloc.cta_group::1.sync.aligned.b32 %0, %1;" \
        :: "r"(tmem), "r"((uint32_t)(ncols)))
#define TCGEN05_COMMIT(mbar) \
    asm volatile("tcgen05.commit.cta_group::1.mbarrier::arrive::one.shared::cluster.b64 [%0];" \
        :: "r"((uint32_t)(mbar)) : "memory")
#define TCGEN05_WAIT_LD() asm volatile("tcgen05.wait::ld.sync.aligned;" ::: "memory")
#define TCGEN05_WAIT_ST() asm volatile("tcgen05.wait::st.sync.aligned;" ::: "memory")
#define TCGEN05_FENCE_AFTER() asm volatile("tcgen05.fence::after_thread_sync;" ::: "memory")
#define TCGEN05_FENCE_BEFORE() asm volatile("tcgen05.fence::before_thread_sync;" ::: "memory")
#define FENCE_ASYNC() asm volatile("fence.proxy.async.shared::cta;" ::: "memory")

#define TCGEN05_LD_X32(r, ta)                                                  \
    asm volatile("tcgen05.ld.sync.aligned.32x32b.x32.b32 "                     \
        "{%0,%1,%2,%3,%4,%5,%6,%7,%8,%9,%10,%11,%12,%13,%14,%15,"             \
        "%16,%17,%18,%19,%20,%21,%22,%23,%24,%25,%26,%27,%28,%29,%30,%31}, [%32];" \
        : "=r"((r)[0]),"=r"((r)[1]),"=r"((r)[2]),"=r"((r)[3]),                 \
          "=r"((r)[4]),"=r"((r)[5]),"=r"((r)[6]),"=r"((r)[7]),                 \
          "=r"((r)[8]),"=r"((r)[9]),"=r"((r)[10]),"=r"((r)[11]),               \
          "=r"((r)[12]),"=r"((r)[13]),"=r"((r)[14]),"=r"((r)[15]),             \
          "=r"((r)[16]),"=r"((r)[17]),"=r"((r)[18]),"=r"((r)[19]),             \
          "=r"((r)[20]),"=r"((r)[21]),"=r"((r)[22]),"=r"((r)[23]),             \
          "=r"((r)[24]),"=r"((r)[25]),"=r"((r)[26]),"=r"((r)[27]),             \
          "=r"((r)[28]),"=r"((r)[29]),"=r"((r)[30]),"=r"((r)[31])              \
        : "r"(ta))

#define TCGEN05_ST_X16(ta, r)                                                  \
    asm volatile("tcgen05.st.sync.aligned.32x32b.x16.b32 [%0], "               \
        "{%1,%2,%3,%4,%5,%6,%7,%8,%9,%10,%11,%12,%13,%14,%15,%16};"           \
        :: "r"(ta),                                                            \
           "r"((r)[0]),"r"((r)[1]),"r"((r)[2]),"r"((r)[3]),                    \
           "r"((r)[4]),"r"((r)[5]),"r"((r)[6]),"r"((r)[7]),                    \
           "r"((r)[8]),"r"((r)[9]),"r"((r)[10]),"r"((r)[11]),                  \
           "r"((r)[12]),"r"((r)[13]),"r"((r)[14]),"r"((r)[15]) : "memory")

#if HAS_TCGEN05
__device__ __forceinline__ uint64_t make_desc(uint32_t addr) {
    const uint64_t base = (uint64_t(2) << 61) | (uint64_t(1) << 46) |
                          (uint64_t(64) << 32) | (uint64_t(1) << 16);
    return base | ((uint64_t)(addr >> 4) & 0x3FFF);
}
__device__ __forceinline__ void mma_f16_ss(uint32_t d, uint64_t a, uint64_t b,
                                           uint32_t idesc, uint32_t en) {
    asm volatile(
        "{ .reg .pred p; setp.ne.u32 p, %4, 0;\n\t"
        "tcgen05.mma.cta_group::1.kind::f16 [%0], %1, %2, %3, {%5,%5,%5,%5}, p; }"
        :: "r"(d), "l"(a), "l"(b), "r"(idesc), "r"(en), "r"(0u) : "memory");
}
__device__ __forceinline__ void mma_f16_ts(uint32_t d, uint32_t a, uint64_t b,
                                           uint32_t idesc, uint32_t en) {
    asm volatile(
        "{ .reg .pred p; setp.ne.u32 p, %4, 0;\n\t"
        "tcgen05.mma.cta_group::1.kind::f16 [%0], [%1], %2, %3, {%5,%5,%5,%5}, p; }"
        :: "r"(d), "r"(a), "l"(b), "r"(idesc), "r"(en), "r"(0u) : "memory");
}
#endif

__device__ __forceinline__ uint32_t pack_bf2(float a, float b) {
    __nv_bfloat162 t = __floats2bfloat162_rn(a, b);
    return *(uint32_t*)&t;
}

// ---------------------------------------------------------------------------
// GEMM config (R14 proven): SS, KC=64, SW128, bulk-B.
// ---------------------------------------------------------------------------
#define GEMM_MT 128
#define GEMM_NT 256
#define GEMM_IDESC ((1u<<4)|(1u<<7)|(1u<<10)|((GEMM_NT/8)<<17)|((GEMM_MT/16)<<24))
#define GEMM_BUF_BYTES 98304
#define GEMM_SMEM_BYTES (1024 + 2 * GEMM_BUF_BYTES)

struct QKVParams {
    const float* A[3];
    const __nv_bfloat16* Wh[3];
    const __nv_bfloat16* Wl[3];
    const float* bias[3];
    __nv_bfloat16* outVth;       // z==2: V^T hi [bh][d][s]
    __nv_bfloat16* outVtl;       // z==2: V^T lo
    __nv_bfloat16* outH[2];      // z==0,1
    __nv_bfloat16* outL[2];
};

#if HAS_TCGEN05
__device__ __forceinline__ void ld_regs_a32(const float* __restrict__ A,
                                            int m0, int k0, float4 (*r)[2],
                                            int tid) {
#pragma unroll
    for (int g = 0; g < 4; g++) {
        int idx = tid + g * 256;
        int row = idx >> 3, seg = idx & 7;
        const float4* p =
            (const float4*)(A + (size_t)(m0 + row) * NE + k0 + seg * 8);
        r[g][0] = p[0];
        r[g][1] = p[1];
    }
}
__device__ __forceinline__ void st_regs_a32(char* sh, char* sl,
                                            float4 (*r)[2], int tid) {
#pragma unroll
    for (int g = 0; g < 4; g++) {
        int idx = tid + g * 256;
        int row = idx >> 3, seg = idx & 7;
        uint32_t off = (uint32_t)(row * 128 + seg * 16);
        off ^= (off >> 3) & 0x70;
        float f[8] = {r[g][0].x, r[g][0].y, r[g][0].z, r[g][0].w,
                      r[g][1].x, r[g][1].y, r[g][1].z, r[g][1].w};
        float rr[8];
        uint4 h, l;
        uint32_t* hp = &h.x;
        uint32_t* lp = &l.x;
#pragma unroll
        for (int e = 0; e < 8; e++) {
            __nv_bfloat16 hb = __float2bfloat16(f[e]);
            rr[e] = f[e] - __bfloat162float(hb);
        }
#pragma unroll
        for (int p2 = 0; p2 < 4; p2++) {
            hp[p2] = pack_bf2(f[p2 * 2], f[p2 * 2 + 1]);
            lp[p2] = pack_bf2(rr[p2 * 2], rr[p2 * 2 + 1]);
        }
        *(uint4*)(sh + off) = h;
        *(uint4*)(sl + off) = l;
    }
}
__device__ __forceinline__ void gemm_issue(uint32_t tmem, uint32_t ba,
                                           int first, uint32_t mbar) {
    FENCE_ASYNC();
    uint64_t dah = make_desc(ba);
    uint64_t dal = make_desc(ba + 16384);
    uint64_t dbh = make_desc(ba + 32768);
    uint64_t dbl = make_desc(ba + 65536);
#pragma unroll
    for (int s = 0; s < 4; s++) {
        uint64_t o2 = 2u * s;
        mma_f16_ss(tmem, dah + o2, dbh + o2, GEMM_IDESC,
                   (!first || s > 0) ? 1u : 0u);
        mma_f16_ss(tmem, dal + o2, dbh + o2, GEMM_IDESC, 1u);
        mma_f16_ss(tmem, dah + o2, dbl + o2, GEMM_IDESC, 1u);
    }
    TCGEN05_COMMIT(mbar);
}
__device__ __forceinline__ void bulk_b(uint32_t dst, uint32_t mbar,
                                       const __nv_bfloat16* Bh,
                                       const __nv_bfloat16* Bl,
                                       int by, int c) {
    const size_t toff = (size_t)(by * 16 + c) * 16384;
    MBARRIER_EXPECT_TX(mbar, 65536);
    CP_BULK(dst + 32768, (const void*)(Bh + toff), 32768, mbar);
    CP_BULK(dst + 65536, (const void*)(Bl + toff), 32768, mbar);
}
#endif

// ---------------------------------------------------------------------------
// Fused QKV projection GEMM: grid (64, 4, 3), 256 threads.
// z==2 epilogue writes V^T hi/lo directly (fused transpose+split).
// ---------------------------------------------------------------------------
__global__ __launch_bounds__(256) void gemm_qkv_kernel(QKVParams P)
{
#if HAS_TCGEN05
    extern __shared__ __align__(1024) char smem[];
    const uint32_t sb = smem_u32(smem);
    const int tid = threadIdx.x;
    const int wid = tid >> 5, lid = tid & 31;
    const int m0 = blockIdx.x * GEMM_MT;
    const int by = blockIdx.y;
    const int n0 = by * GEMM_NT;
    const int z = blockIdx.z;
    const float* A = P.A[z];
    const __nv_bfloat16* Bh = P.Wh[z];
    const __nv_bfloat16* Bl = P.Wl[z];
    const float* bias = P.bias[z];

    if (wid == 0) TCGEN05_ALLOC(sb, 512);
    if (tid == 0) {
        MBARRIER_INIT(sb + 16, 1); MBARRIER_INIT(sb + 24, 1);
        MBARRIER_INIT(sb + 32, 1); MBARRIER_INIT(sb + 40, 1);
    }
    __syncthreads();
    uint32_t tmem;
    asm volatile("ld.shared.b32 %0, [%1];" : "=r"(tmem) : "r"(sb));

    if (wid == 0 && elect_one()) {
        bulk_b(sb + 1024, sb + 32, Bh, Bl, by, 0);
        bulk_b(sb + 1024 + GEMM_BUF_BYTES, sb + 40, Bh, Bl, by, 1);
    }
    float4 rA[4][2];
    ld_regs_a32(A, m0, 0, rA, tid);

    int ph0 = 0, ph1 = 0, pht0 = 0, pht1 = 0;
    for (int c = 0; c < 16; c++) {
        const int buf = c & 1;
        char* bs = smem + 1024 + buf * GEMM_BUF_BYTES;
        if (c >= 2) {
            if (buf == 0) { MBARRIER_WAIT_PARITY(sb + 16, ph0); ph0 ^= 1; }
            else          { MBARRIER_WAIT_PARITY(sb + 24, ph1); ph1 ^= 1; }
            if (wid == 0 && elect_one())
                bulk_b(sb + 1024 + buf * GEMM_BUF_BYTES,
                       sb + 32 + buf * 8, Bh, Bl, by, c);
        }
        st_regs_a32(bs, bs + 16384, rA, tid);
        if (c < 15) ld_regs_a32(A, m0, (c + 1) * 64, rA, tid);
        __syncthreads();
        if (wid == 0 && elect_one()) {
            if (buf == 0) { MBARRIER_WAIT_PARITY(sb + 32, pht0); pht0 ^= 1; }
            else          { MBARRIER_WAIT_PARITY(sb + 40, pht1); pht1 ^= 1; }
            gemm_issue(tmem, sb + 1024 + buf * GEMM_BUF_BYTES, c == 0,
                       sb + 16 + buf * 8);
        }
    }
    MBARRIER_WAIT_PARITY(sb + 16, ph0);
    MBARRIER_WAIT_PARITY(sb + 24, ph1);
    TCGEN05_FENCE_AFTER();

    const int m = m0 + 32 * (wid & 3) + lid;
    const int b = m >> 11, s_ = m & (NS - 1);
    const int chalf = (wid >> 2) * 128;
#pragma unroll
    for (int i = 0; i < 4; i++) {
        uint32_t r[32];
        TCGEN05_LD_X32(r, tmem + chalf + i * 32);
        TCGEN05_WAIT_LD();
        const int nbase = n0 + chalf + i * 32;
        float vals[32];
        const float4* bp = (const float4*)(bias + nbase);
#pragma unroll
        for (int j4 = 0; j4 < 8; j4++) {
            float4 bb = bp[j4];
            vals[j4 * 4 + 0] = __uint_as_float(r[j4 * 4 + 0]) + bb.x;
            vals[j4 * 4 + 1] = __uint_as_float(r[j4 * 4 + 1]) + bb.y;
            vals[j4 * 4 + 2] = __uint_as_float(r[j4 * 4 + 2]) + bb.z;
            vals[j4 * 4 + 3] = __uint_as_float(r[j4 * 4 + 3]) + bb.w;
        }
        const int h = nbase >> 6, d0 = nbase & 63;
        if (z == 2) {
            // fused V^T + hi/lo split: [bh][d][s], warp-coalesced over s
            __nv_bfloat16* vtb = P.outVth +
                ((size_t)(b * NH + h) * ND + d0) * NS + s_;
            __nv_bfloat16* vlb = P.outVtl +
                ((size_t)(b * NH + h) * ND + d0) * NS + s_;
#pragma unroll
            for (int j = 0; j < 32; j++) {
                float x = vals[j];
                __nv_bfloat16 hi = __float2bfloat16(x);
                vtb[(size_t)j * NS] = hi;
                vlb[(size_t)j * NS] = __float2bfloat16(x - __bfloat162float(hi));
            }
        } else {
            const size_t base = ((size_t)(b * NH + h) * NS + s_) * ND + d0;
#pragma unroll
            for (int c8 = 0; c8 < 4; c8++) {
                uint4 wh, wl;
                uint32_t* ph_ = &wh.x;
                uint32_t* pl_ = &wl.x;
#pragma unroll
                for (int p2 = 0; p2 < 4; p2++) {
                    float a = vals[c8 * 8 + p2 * 2];
                    float bv = vals[c8 * 8 + p2 * 2 + 1];
                    __nv_bfloat16 ha = __float2bfloat16(a);
                    __nv_bfloat16 hb = __float2bfloat16(bv);
                    ph_[p2] = pack_bf2(a, bv);
                    pl_[p2] = pack_bf2(a - __bfloat162float(ha),
                                       bv - __bfloat162float(hb));
                }
                *(uint4*)(P.outH[z] + base + c8 * 8) = wh;
                *(uint4*)(P.outL[z] + base + c8 * 8) = wl;
            }
        }
    }
    __syncthreads();
    if (wid == 0) TCGEN05_DEALLOC(tmem, 512);
#else
    (void)P;
#endif
}

// ---------------------------------------------------------------------------
// Output projection GEMM (R14): grid (64,4), 256 threads.
// ---------------------------------------------------------------------------
__global__ __launch_bounds__(256) void gemm_ctx_kernel(
    const __nv_bfloat16* __restrict__ Ah, const __nv_bfloat16* __restrict__ Al,
    const __nv_bfloat16* __restrict__ Bh, const __nv_bfloat16* __restrict__ Bl,
    const float* __restrict__ bias, float* __restrict__ out)
{
#if HAS_TCGEN05
    extern __shared__ __align__(1024) char smem[];
    const uint32_t sb = smem_u32(smem);
    const int tid = threadIdx.x;
    const int wid = tid >> 5, lid = tid & 31;
    const int m0 = blockIdx.x * GEMM_MT;
    const int by = blockIdx.y;
    const int n0 = by * GEMM_NT;

    if (wid == 0) TCGEN05_ALLOC(sb, 512);
    if (tid == 0) {
        MBARRIER_INIT(sb + 16, 1); MBARRIER_INIT(sb + 24, 1);
        MBARRIER_INIT(sb + 32, 1); MBARRIER_INIT(sb + 40, 1);
    }
    __syncthreads();
    uint32_t tmem;
    asm volatile("ld.shared.b32 %0, [%1];" : "=r"(tmem) : "r"(sb));

    if (wid == 0 && elect_one()) {
        bulk_b(sb + 1024, sb + 32, Bh, Bl, by, 0);
        bulk_b(sb + 1024 + GEMM_BUF_BYTES, sb + 40, Bh, Bl, by, 1);
    }

    uint4 rAh[4], rAl[4];
    auto ldA = [&](int k0) {
#pragma unroll
        for (int it = 0; it < 4; it++) {
            int idx = tid + it * 256;
            int row = idx >> 3, q = idx & 7;
            rAh[it] = *((const uint4*)(Ah + (size_t)(m0 + row) * NE + k0) + q);
            rAl[it] = *((const uint4*)(Al + (size_t)(m0 + row) * NE + k0) + q);
        }
    };
    auto stA = [&](char* sh, char* sl) {
#pragma unroll
        for (int it = 0; it < 4; it++) {
            int idx = tid + it * 256;
            int row = idx >> 3, q = idx & 7;
            uint32_t off = (uint32_t)(row * 128 + q * 16);
            off ^= (off >> 3) & 0x70;
            *(uint4*)(sh + off) = rAh[it];
            *(uint4*)(sl + off) = rAl[it];
        }
    };
    ldA(0);

    int ph0 = 0, ph1 = 0, pht0 = 0, pht1 = 0;
    for (int c = 0; c < 16; c++) {
        const int buf = c & 1;
        char* bs = smem + 1024 + buf * GEMM_BUF_BYTES;
        if (c >= 2) {
            if (buf == 0) { MBARRIER_WAIT_PARITY(sb + 16, ph0); ph0 ^= 1; }
            else          { MBARRIER_WAIT_PARITY(sb + 24, ph1); ph1 ^= 1; }
            if (wid == 0 && elect_one())
                bulk_b(sb + 1024 + buf * GEMM_BUF_BYTES,
                       sb + 32 + buf * 8, Bh, Bl, by, c);
        }
        stA(bs, bs + 16384);
        if (c < 15) ldA((c + 1) * 64);
        __syncthreads();
        if (wid == 0 && elect_one()) {
            if (buf == 0) { MBARRIER_WAIT_PARITY(sb + 32, pht0); pht0 ^= 1; }
            else          { MBARRIER_WAIT_PARITY(sb + 40, pht1); pht1 ^= 1; }
            gemm_issue(tmem, sb + 1024 + buf * GEMM_BUF_BYTES, c == 0,
                       sb + 16 + buf * 8);
        }
    }
    MBARRIER_WAIT_PARITY(sb + 16, ph0);
    MBARRIER_WAIT_PARITY(sb + 24, ph1);
    TCGEN05_FENCE_AFTER();

    const int m = m0 + 32 * (wid & 3) + lid;
    const int chalf = (wid >> 2) * 128;
#pragma unroll
    for (int i = 0; i < 4; i++) {
        uint32_t r[32];
        TCGEN05_LD_X32(r, tmem + chalf + i * 32);
        TCGEN05_WAIT_LD();
        const int nbase = n0 + chalf + i * 32;
        const float4* bp = (const float4*)(bias + nbase);
        float* dst = out + ((size_t)m * NE + nbase);
#pragma unroll
        for (int j4 = 0; j4 < 8; j4++) {
            float4 bb = bp[j4];
            float4 w;
            w.x = __uint_as_float(r[j4 * 4 + 0]) + bb.x;
            w.y = __uint_as_float(r[j4 * 4 + 1]) + bb.y;
            w.z = __uint_as_float(r[j4 * 4 + 2]) + bb.z;
            w.w = __uint_as_float(r[j4 * 4 + 3]) + bb.w;
            *(float4*)(dst + j4 * 4) = w;
        }
    }
    __syncthreads();
    if (wid == 0) TCGEN05_DEALLOC(tmem, 512);
#else
    (void)Ah;(void)Al;(void)Bh;(void)Bl;(void)bias;(void)out;
#endif
}

// ---------------------------------------------------------------------------
// tcgen05 flash attention (R14): P packed into TMEM (STTM), O-MMA TS mode,
// 2-stage KV, bounds(256,2).
// TMEM (256 cols): S 0-63, O 64-127, Ph 128-159, Pl 160-191.
// ---------------------------------------------------------------------------
#define AT_Q   1024
#define AT_QL  (AT_Q + 16384)
#define AT_STG (AT_QL + 16384)            // 2 stages x 32KB: Kh,Kl,Vh,Vl
#define AT_SMEM_BYTES (AT_STG + 2 * 32768)   // 99,328 B
#define AT_IDESC ((1u<<4)|(1u<<7)|(1u<<10)|((64/8)<<17)|((128/16)<<24))

__global__ __launch_bounds__(256, 2) void attn_mma_kernel(
    const __nv_bfloat16* __restrict__ qh, const __nv_bfloat16* __restrict__ ql,
    const __nv_bfloat16* __restrict__ kh, const __nv_bfloat16* __restrict__ kl,
    const __nv_bfloat16* __restrict__ vth, const __nv_bfloat16* __restrict__ vtl,
    const float* __restrict__ bias,
    __nv_bfloat16* __restrict__ ctx_h, __nv_bfloat16* __restrict__ ctx_l)
{
#if HAS_TCGEN05
    extern __shared__ __align__(1024) char smem[];
    const uint32_t sb = smem_u32(smem);
    const int tid = threadIdx.x;
    const int wid = tid >> 5, lid = tid & 31;
    const int s0 = blockIdx.x * 128;
    const int bh = blockIdx.y;

    const __nv_bfloat16* qhp = qh + ((size_t)bh * NS + s0) * ND;
    const __nv_bfloat16* qlp = ql + ((size_t)bh * NS + s0) * ND;
    const __nv_bfloat16* khp = kh + (size_t)bh * NS * ND;
    const __nv_bfloat16* klp = kl + (size_t)bh * NS * ND;
    const __nv_bfloat16* vhp = vth + (size_t)bh * ND * NS;
    const __nv_bfloat16* vlp = vtl + (size_t)bh * ND * NS;

    if (wid == 0) TCGEN05_ALLOC(sb, 256);
    if (tid == 0) { MBARRIER_INIT(sb + 16, 1); MBARRIER_INIT(sb + 24, 1); }
    __syncthreads();
    uint32_t tmem;
    asm volatile("ld.shared.b32 %0, [%1];" : "=r"(tmem) : "r"(sb));

#pragma unroll
    for (int it = 0; it < 4; it++) {
        int idx = tid + it * 256;
        int row = idx >> 3, q = idx & 7;
        uint32_t off = (uint32_t)(row * 128 + q * 16);
        off ^= (off >> 3) & 0x70;
        *(uint4*)(smem + AT_Q + off)  = *((const uint4*)(qhp + (size_t)row * ND) + q);
        *(uint4*)(smem + AT_QL + off) = *((const uint4*)(qlp + (size_t)row * ND) + q);
    }

    auto ld_kv = [&](int t, int stg) {
        char* ks = smem + AT_STG + stg * 32768;
        const __nv_bfloat16* kh_t = khp + (size_t)t * 64 * ND;
        const __nv_bfloat16* kl_t = klp + (size_t)t * 64 * ND;
        const __nv_bfloat16* vh_t = vhp + (size_t)t * 64;
        const __nv_bfloat16* vl_t = vlp + (size_t)t * 64;
#pragma unroll
        for (int it = 0; it < 2; it++) {
            int idx = tid + it * 256;
            int row = idx >> 3, q = idx & 7;
            uint32_t off = (uint32_t)(row * 128 + q * 16);
            off ^= (off >> 3) & 0x70;
            *(uint4*)(ks + off)         = *((const uint4*)(kh_t + (size_t)row * ND) + q);
            *(uint4*)(ks + 8192 + off)  = *((const uint4*)(kl_t + (size_t)row * ND) + q);
            *(uint4*)(ks + 16384 + off) = *((const uint4*)(vh_t + (size_t)row * NS) + q);
            *(uint4*)(ks + 24576 + off) = *((const uint4*)(vl_t + (size_t)row * NS) + q);
        }
    };

    const uint64_t dq_h = make_desc(sb + AT_Q);
    const uint64_t dq_l = make_desc(sb + AT_QL);

    auto issue_S = [&](int t) {
        const uint32_t ks = sb + AT_STG + (t & 1) * 32768;
        uint64_t dk_h = make_desc(ks), dk_l = make_desc(ks + 8192);
#pragma unroll
        for (int s4 = 0; s4 < 4; s4++) {
            uint64_t o2 = 2u * s4;
            mma_f16_ss(tmem, dq_h + o2, dk_h + o2, AT_IDESC, s4 > 0 ? 1u : 0u);
            mma_f16_ss(tmem, dq_l + o2, dk_h + o2, AT_IDESC, 1u);
            mma_f16_ss(tmem, dq_h + o2, dk_l + o2, AT_IDESC, 1u);
        }
    };
    auto issue_O = [&](int t) {
        const uint32_t ks = sb + AT_STG + (t & 1) * 32768;
        uint64_t dv_h = make_desc(ks + 16384), dv_l = make_desc(ks + 24576);
        const uint32_t p_h = tmem + 128, p_l = tmem + 160;
#pragma unroll
        for (int s4 = 0; s4 < 4; s4++) {
            uint64_t o2 = 2u * s4;
            uint32_t ao = s4 * 8;
            mma_f16_ts(tmem + 64, p_h + ao, dv_h + o2, AT_IDESC,
                       (t > 0 || s4 > 0) ? 1u : 0u);
            mma_f16_ts(tmem + 64, p_l + ao, dv_h + o2, AT_IDESC, 1u);
            mma_f16_ts(tmem + 64, p_h + ao, dv_l + o2, AT_IDESC, 1u);
        }
    };

    ld_kv(0, 0);
    __syncthreads();
    if (wid == 0 && elect_one()) {
        FENCE_ASYNC();
        issue_S(0);
        TCGEN05_COMMIT(sb + 16);
    }

    const int srow = (wid & 3) * 32 + lid;
    const int shf = wid >> 2;
    const uint32_t warp_off = (uint32_t)(wid & 3) << 21;
    const float* brow = bias + (size_t)(s0 + srow) * NS;
    float lsum = 0.f;
    int ph_s = 0, ph_o = 0;

    for (int t = 0; t < 32; t++) {
        float4 bb[8];
        const float4* bp = (const float4*)(brow + t * 64 + shf * 32);
#pragma unroll
        for (int i = 0; i < 8; i++) bb[i] = bp[i];

        MBARRIER_WAIT_PARITY(sb + 16, ph_s);   // S(t) done
        ph_s ^= 1;
        TCGEN05_FENCE_AFTER();

        uint32_t r[32];
        TCGEN05_LD_X32(r, tmem + shf * 32);
        TCGEN05_WAIT_LD();
        float p[32];
#pragma unroll
        for (int j4 = 0; j4 < 8; j4++) {
            float4 b4 = bb[j4];
            p[j4*4+0] = __expf(fmaf(__uint_as_float(r[j4*4+0]), 0.125f, b4.x));
            p[j4*4+1] = __expf(fmaf(__uint_as_float(r[j4*4+1]), 0.125f, b4.y));
            p[j4*4+2] = __expf(fmaf(__uint_as_float(r[j4*4+2]), 0.125f, b4.z));
            p[j4*4+3] = __expf(fmaf(__uint_as_float(r[j4*4+3]), 0.125f, b4.w));
            lsum += p[j4*4+0] + p[j4*4+1] + p[j4*4+2] + p[j4*4+3];
        }

        if (t >= 1) {                          // O(t-1) done reading P, V(t-1)
            MBARRIER_WAIT_PARITY(sb + 24, ph_o);
            ph_o ^= 1;
        }

        {
            uint32_t phh[16], pll[16];
#pragma unroll
            for (int i = 0; i < 16; i++) {
                float a = p[2 * i], c = p[2 * i + 1];
                __nv_bfloat16 ha = __float2bfloat16(a);
                __nv_bfloat16 hc = __float2bfloat16(c);
                phh[i] = pack_bf2(a, c);
                pll[i] = pack_bf2(a - __bfloat162float(ha),
                                  c - __bfloat162float(hc));
            }
            TCGEN05_ST_X16(tmem + 128 + shf * 16 + warp_off, phh);
            TCGEN05_ST_X16(tmem + 160 + shf * 16 + warp_off, pll);
            TCGEN05_WAIT_ST();
        }

        if (t + 1 < 32) ld_kv(t + 1, (t + 1) & 1);

        TCGEN05_FENCE_BEFORE();
        __syncthreads();

        if (wid == 0 && elect_one()) {
            FENCE_ASYNC();
            TCGEN05_FENCE_AFTER();
            if (t + 1 < 32) {
                issue_S(t + 1);
                TCGEN05_COMMIT(sb + 16);
            }
            issue_O(t);
            TCGEN05_COMMIT(sb + 24);
        }
    }
    MBARRIER_WAIT_PARITY(sb + 24, ph_o);       // O(31)
    TCGEN05_FENCE_AFTER();

    *(float*)(smem + AT_Q + tid * 4) = lsum;
    __syncthreads();
    const float lother = *(const float*)(smem + AT_Q + (tid ^ 128) * 4);
    const float inv = 1.f / (lsum + lother);

    const int b = bh >> 4, h = bh & 15;
    const size_t obase = ((size_t)b * NS + s0 + srow) * NE + h * ND + shf * 32;
    uint32_t r[32];
    TCGEN05_LD_X32(r, tmem + 64 + shf * 32);
    TCGEN05_WAIT_LD();
#pragma unroll
    for (int c8 = 0; c8 < 4; c8++) {
        uint4 wh, wl;
        uint32_t* phh = &wh.x;
        uint32_t* pll = &wl.x;
#pragma unroll
        for (int p2 = 0; p2 < 4; p2++) {
            float a = __uint_as_float(r[c8 * 8 + p2 * 2]) * inv;
            float c = __uint_as_float(r[c8 * 8 + p2 * 2 + 1]) * inv;
            __nv_bfloat16 ha = __float2bfloat16(a);
            __nv_bfloat16 hc = __float2bfloat16(c);
            phh[p2] = pack_bf2(a, c);
            pll[p2] = pack_bf2(a - __bfloat162float(ha),
                               c - __bfloat162float(hc));
        }
        *(uint4*)(ctx_h + obase + c8 * 8) = wh;
        *(uint4*)(ctx_l + obase + c8 * 8) = wl;
    }
    TCGEN05_FENCE_BEFORE();
    __syncthreads();
    if (wid == 0) TCGEN05_DEALLOC(tmem, 256);
#else
    (void)qh;(void)ql;(void)kh;(void)kl;(void)vth;(void)vtl;(void)bias;(void)ctx_h;(void)ctx_l;
#endif
}

// ---------------------------------------------------------------------------
// Weight transpose + split into TILED layout
// ---------------------------------------------------------------------------
__global__ __launch_bounds__(256) void transpose_split_tiled_kernel(
    const float* __restrict__ in, __nv_bfloat16* __restrict__ oh,
    __nv_bfloat16* __restrict__ ol, int C)
{
    __shared__ float t[64][65];
    const float* inz = in + (size_t)blockIdx.z * NE * C;
    const int r0 = blockIdx.x * 64, c0 = blockIdx.y * 64;
    const int tid = threadIdx.x;
#pragma unroll
    for (int it = 0; it < 16; it++) {
        int idx = tid + it * 256;
        int rr = idx >> 6, cc = idx & 63;
        t[rr][cc] = inz[(size_t)(r0 + rr) * C + c0 + cc];
    }
    __syncthreads();
#pragma unroll
    for (int it = 0; it < 16; it++) {
        int idx = tid + it * 256;
        int cc = idx >> 6, rr = idx & 63;
        float x = t[rr][cc];
        __nv_bfloat16 hi = __float2bfloat16(x);
        const int n = blockIdx.z * C + c0 + cc;
        const int k = r0 + rr;
        uint32_t off = (uint32_t)((n & 255) * 128 + (k & 63) * 2);
        off ^= (off >> 3) & 0x70;
        const size_t base = ((size_t)((n >> 8) * 16 + (k >> 6))) * 32768 + off;
        *(__nv_bfloat16*)((char*)oh + base) = hi;
        *(__nv_bfloat16*)((char*)ol + base) =
            __float2bfloat16(x - __bfloat162float(hi));
    }
}

// ---------------------------------------------------------------------------

extern "C" void kernel_launch(void* const* d_in, const int* in_sizes, int n_in,
                              void* d_out, int out_size)
{
    const float* query = (const float*)d_in[0];
    const float* key_  = (const float*)d_in[1];
    const float* value = (const float*)d_in[2];
    const float* abias = (const float*)d_in[3];
    const float* Wq = (const float*)d_in[4];
    const float* bq = (const float*)d_in[5];
    const float* Wk = (const float*)d_in[6];
    const float* bk = (const float*)d_in[7];
    const float* Wv = (const float*)d_in[8];
    const float* bv = (const float*)d_in[9];
    const float* Wo = (const float*)d_in[10];
    const float* bo = (const float*)d_in[11];
    float* out = (float*)d_out;

    __nv_bfloat16 *qh, *ql, *kh, *kl, *vth, *vtl, *ah, *al, *wth, *wtl;
    cudaGetSymbolAddress((void**)&qh, g_qh);
    cudaGetSymbolAddress((void**)&ql, g_ql);
    cudaGetSymbolAddress((void**)&kh, g_kh);
    cudaGetSymbolAddress((void**)&kl, g_kl);
    cudaGetSymbolAddress((void**)&vth, g_vth);
    cudaGetSymbolAddress((void**)&vtl, g_vtl);
    cudaGetSymbolAddress((void**)&ah, g_ah);
    cudaGetSymbolAddress((void**)&al, g_al);
    cudaGetSymbolAddress((void**)&wth, g_wth);
    cudaGetSymbolAddress((void**)&wtl, g_wtl);

    cudaFuncSetAttribute(gemm_qkv_kernel,
                         cudaFuncAttributeMaxDynamicSharedMemorySize,
                         GEMM_SMEM_BYTES);
    cudaFuncSetAttribute(gemm_ctx_kernel,
                         cudaFuncAttributeMaxDynamicSharedMemorySize,
                         GEMM_SMEM_BYTES);
    cudaFuncSetAttribute(attn_mma_kernel,
                         cudaFuncAttributeMaxDynamicSharedMemorySize,
                         AT_SMEM_BYTES);

    // weight transposes into TILED layout (hi/lo)
    dim3 gw(16, 1, 16);
    transpose_split_tiled_kernel<<<gw, 256>>>(Wq, wth + 0 * NE * NE,
                                              wtl + 0 * NE * NE, ND);
    transpose_split_tiled_kernel<<<gw, 256>>>(Wk, wth + 1 * NE * NE,
                                              wtl + 1 * NE * NE, ND);
    transpose_split_tiled_kernel<<<gw, 256>>>(Wv, wth + 2 * NE * NE,
                                              wtl + 2 * NE * NE, ND);

    // fused QKV projections (z==2 writes V^T hi/lo directly)
    QKVParams P;
    P.A[0] = query; P.A[1] = key_; P.A[2] = value;
    P.Wh[0] = wth; P.Wh[1] = wth + NE * NE; P.Wh[2] = wth + 2 * NE * NE;
    P.Wl[0] = wtl; P.Wl[1] = wtl + NE * NE; P.Wl[2] = wtl + 2 * NE * NE;
    P.bias[0] = bq; P.bias[1] = bk; P.bias[2] = bv;
    P.outVth = vth; P.outVtl = vtl;
    P.outH[0] = qh; P.outH[1] = kh;
    P.outL[0] = ql; P.outL[1] = kl;
    gemm_qkv_kernel<<<dim3(64, 4, 3), 256, GEMM_SMEM_BYTES>>>(P);

    // attention -> ctx bf16 hi/lo (V^T already produced by the fused epilogue)
    attn_mma_kernel<<<dim3(16, 64), 256, AT_SMEM_BYTES>>>(
        qh, ql, kh, kl, vth, vtl, abias, ah, al);

    // output projection (Wo tiled into slot 0)
    transpose_split_tiled_kernel<<<dim3(16, 16, 1), 256>>>(Wo, wth, wtl, NE);
    gemm_ctx_kernel<<<dim3(64, 4), 256, GEMM_SMEM_BYTES>>>(ah, al, wth, wtl, bo, out);
}